// round 1
// baseline (speedup 1.0000x reference)
#include <cuda_runtime.h>
#include <math.h>

#define BDIM 512
#define NTOK 256
#define CDIM 256
#define HNUM 8
#define HD   32

// ---------------- scratch (device globals; no allocation allowed) ----------
__device__ float g_bq[HNUM * NTOK * 32];
__device__ float g_bk[HNUM * NTOK * 32];
__device__ float g_bias[HNUM * NTOK * NTOK];          // 2 MB
__device__ float g_q[BDIM * HNUM * NTOK * HD];        // 134 MB
__device__ float g_k[BDIM * HNUM * NTOK * HD];
__device__ float g_v[BDIM * HNUM * NTOK * HD];
__device__ float g_att[BDIM * NTOK * CDIM];           // 134 MB

// ---------------- packed f32x2 helpers (sm_103a) ---------------------------
__device__ __forceinline__ unsigned long long pk2(float x, float y) {
    unsigned long long r;
    asm("mov.b64 %0, {%1, %2};" : "=l"(r) : "f"(x), "f"(y));
    return r;
}
__device__ __forceinline__ void fma2(unsigned long long& c, unsigned long long a, unsigned long long b) {
    asm("fma.rn.f32x2 %0, %1, %2, %0;" : "+l"(c) : "l"(a), "l"(b));
}
__device__ __forceinline__ float2 up2(unsigned long long v) {
    float2 f;
    asm("mov.b64 {%0, %1}, %2;" : "=f"(f.x), "=f"(f.y) : "l"(v));
    return f;
}

// ---------------- kernel 1: MLP -> bq, bk ---------------------------------
// grid 256 (one block per token n), 128 threads
__global__ __launch_bounds__(128) void bias_mlp_kernel(
    const float* __restrict__ m1w, const float* __restrict__ m1b,
    const float* __restrict__ m2w, const float* __restrict__ bs) {
    __shared__ float hf[128];
    const int n = blockIdx.x;
    const int t = threadIdx.x;
    const float invden = 1.0f / log1pf(15.0f);
    const float cy = log1pf((float)(n >> 4)) * invden;
    const float cx = log1pf((float)(n & 15)) * invden;
    {
        float z = cy * m1w[t] + cx * m1w[128 + t] + m1b[t];
        hf[t] = 0.5f * z * (1.0f + erff(z * 0.70710678118654752f));  // exact gelu
    }
    __syncthreads();
    const float bscale = bs[0];
    for (int c = t; c < 512; c += 128) {
        float acc = 0.0f;
        #pragma unroll 8
        for (int j = 0; j < 128; j++) acc += hf[j] * m2w[j * 512 + c];
        float sig = 1.0f / (1.0f + __expf(-acc));
        int h = c >> 6, s = (c >> 5) & 1, r = c & 31;
        if (s == 0) g_bq[(h * NTOK + n) * 32 + r] = bscale * sig;
        else        g_bk[(h * NTOK + n) * 32 + r] = sig;
    }
}

// ---------------- kernel 2: bias[h,n,m] = bq[h,n,:] . bk[h,m,:] ------------
// grid 2048 (h*256+n), 256 threads (m)
__global__ __launch_bounds__(256) void bias_outer_kernel() {
    const int hn = blockIdx.x;
    const int h = hn >> 8, n = hn & 255;
    __shared__ float q[32];
    const int t = threadIdx.x;
    if (t < 32) q[t] = g_bq[(h * NTOK + n) * 32 + t];
    __syncthreads();
    const float* bkrow = &g_bk[h * (NTOK * 32) + t * 32];
    float acc = 0.0f;
    #pragma unroll
    for (int r = 0; r < 32; r++) acc += q[r] * bkrow[r];
    g_bias[h * (NTOK * NTOK) + n * NTOK + t] = acc;
}

// ---------------- kernel 3: QKV GEMM [131072,256] x [256,768] --------------
// 64x64 tile, BK=16, 256 threads, 4x4 micro-tile, packed f32x2 FMA
__global__ __launch_bounds__(256) void gemm_qkv_kernel(
    const float* __restrict__ A, const float* __restrict__ W,
    const float* __restrict__ qb, const float* __restrict__ ls) {
    __shared__ float As[16][65];
    __shared__ float Bs[16][64];
    const int t = threadIdx.x;
    const int tx = t & 15, ty = t >> 4;
    const int m0 = blockIdx.y << 6, c0 = blockIdx.x << 6;
    const int la_row = t >> 2, la_k = (t & 3) << 2;
    const int lb_k = t >> 4, lb_c = (t & 15) << 2;

    unsigned long long acc[4][2];
    #pragma unroll
    for (int i = 0; i < 4; i++) { acc[i][0] = 0ULL; acc[i][1] = 0ULL; }

    for (int k0 = 0; k0 < 256; k0 += 16) {
        float4 a  = *(const float4*)&A[(size_t)(m0 + la_row) * 256 + k0 + la_k];
        float4 bb = *(const float4*)&W[(size_t)(k0 + lb_k) * 768 + c0 + lb_c];
        As[la_k + 0][la_row] = a.x; As[la_k + 1][la_row] = a.y;
        As[la_k + 2][la_row] = a.z; As[la_k + 3][la_row] = a.w;
        *(float4*)&Bs[lb_k][lb_c] = bb;
        __syncthreads();
        #pragma unroll
        for (int k = 0; k < 16; k++) {
            float4 b4 = *(const float4*)&Bs[k][tx << 2];
            unsigned long long b01 = pk2(b4.x, b4.y);
            unsigned long long b23 = pk2(b4.z, b4.w);
            #pragma unroll
            for (int i = 0; i < 4; i++) {
                float av = As[k][(ty << 2) + i];
                unsigned long long aa = pk2(av, av);
                fma2(acc[i][0], aa, b01);
                fma2(acc[i][1], aa, b23);
            }
        }
        __syncthreads();
    }

    const int s = c0 >> 8;  // 0=q, 1=k, 2=v (constant per block since 64 | 256)
    float* dst = (s == 0) ? g_q : (s == 1 ? g_k : g_v);
    #pragma unroll
    for (int i = 0; i < 4; i++) {
        int row = m0 + (ty << 2) + i;
        int bidx = row >> 8, n = row & 255;
        float2 v01 = up2(acc[i][0]), v23 = up2(acc[i][1]);
        float vals[4] = {v01.x, v01.y, v23.x, v23.y};
        #pragma unroll
        for (int j = 0; j < 4; j++) {
            int c = c0 + (tx << 2) + j;
            float v = vals[j] + qb[c];
            int rem = c & 255;
            int h = rem >> 5, d = rem & 31;
            if (s == 0) v *= ls[h];
            dst[(size_t)((bidx * 8 + h) * 256 + n) * 32 + d] = v;
        }
    }
}

// ---------------- kernel 4: attention per (b,h) ----------------------------
// 256 threads, dynamic smem: kT[32][260] + v[256][33] + probs4[8][256] + q4[8][32]
#define ATTN_SMEM_FLOATS (32 * 260 + 256 * 33 + 8 * 256 * 4 + 8 * 32 * 4 + 32 + 256)
#define ATTN_SMEM_BYTES  (ATTN_SMEM_FLOATS * 4)

__device__ __forceinline__ float softmax_row(float* s) {
    float m = s[0];
    #pragma unroll
    for (int i = 1; i < 8; i++) m = fmaxf(m, s[i]);
    #pragma unroll
    for (int o = 16; o > 0; o >>= 1) m = fmaxf(m, __shfl_xor_sync(0xffffffffu, m, o));
    float sum = 0.0f;
    #pragma unroll
    for (int i = 0; i < 8; i++) { s[i] = __expf(s[i] - m); sum += s[i]; }
    #pragma unroll
    for (int o = 16; o > 0; o >>= 1) sum += __shfl_xor_sync(0xffffffffu, sum, o);
    return 1.0f / sum;
}

__global__ __launch_bounds__(256) void attn_kernel(const float* __restrict__ vrs) {
    extern __shared__ float sm[];
    float* kT    = sm;                    // [32][260] k transposed, pad 260
    float* sv    = kT + 32 * 260;         // [256][33] v, pad 33
    float* pr    = sv + 256 * 33;         // [8 warps][256][4]  (float4 per j)
    float* sq    = pr + 8 * 256 * 4;      // [8 warps][32][4]   (float4 per d)
    float* vmean = sq + 8 * 32 * 4;       // [32] (pre-scaled by val_res_scale)
    float* part  = vmean + 32;            // [8][32]

    const int bh = blockIdx.x;
    const int b = bh >> 3, h = bh & 7;
    const float* qp = g_q + (size_t)bh * (NTOK * HD);
    const float* kp = g_k + (size_t)bh * (NTOK * HD);
    const float* vp = g_v + (size_t)bh * (NTOK * HD);
    const float* bp = g_bias + h * (NTOK * NTOK);
    const int t = threadIdx.x, w = t >> 5, lane = t & 31;

    // stage K (transposed) and V into smem, coalesced float4 global reads
    for (int i = t; i < 2048; i += 256) {
        float4 kk = ((const float4*)kp)[i];
        float4 vv = ((const float4*)vp)[i];
        int n = i >> 3, d = (i & 7) << 2;
        kT[(d + 0) * 260 + n] = kk.x; kT[(d + 1) * 260 + n] = kk.y;
        kT[(d + 2) * 260 + n] = kk.z; kT[(d + 3) * 260 + n] = kk.w;
        sv[n * 33 + d + 0] = vv.x; sv[n * 33 + d + 1] = vv.y;
        sv[n * 33 + d + 2] = vv.z; sv[n * 33 + d + 3] = vv.w;
    }
    __syncthreads();

    // v_mean (column means), pre-multiplied by val_res_scale[h]
    {
        float s = 0.0f;
        int base = w << 5;
        #pragma unroll
        for (int r = 0; r < 32; r++) s += sv[(base + r) * 33 + lane];
        part[(w << 5) + lane] = s;
    }
    __syncthreads();
    if (t < 32) {
        float s = 0.0f;
        #pragma unroll
        for (int g = 0; g < 8; g++) s += part[(g << 5) + t];
        vmean[t] = s * (1.0f / 256.0f) * vrs[h];
    }
    __syncthreads();

    float4* sq4 = (float4*)sq;   // [8][32]
    float4* pr4 = (float4*)pr;   // [8][256]

    for (int pass = 0; pass < 8; pass++) {
        const int r0 = (pass << 5) + (w << 2);   // this warp's 4 query rows

        // stage 4 q rows, packed as float4 per d
        float4 qv;
        qv.x = qp[(r0 + 0) * 32 + lane];
        qv.y = qp[(r0 + 1) * 32 + lane];
        qv.z = qp[(r0 + 2) * 32 + lane];
        qv.w = qp[(r0 + 3) * 32 + lane];
        sq4[(w << 5) + lane] = qv;
        __syncwarp();

        // scores for 4 rows; lane handles j = lane + 32*tt
        float s0[8], s1[8], s2[8], s3[8];
        #pragma unroll
        for (int tt = 0; tt < 8; tt++) {
            int j = (tt << 5) + lane;
            s0[tt] = bp[(r0 + 0) * 256 + j];
            s1[tt] = bp[(r0 + 1) * 256 + j];
            s2[tt] = bp[(r0 + 2) * 256 + j];
            s3[tt] = bp[(r0 + 3) * 256 + j];
        }
        #pragma unroll 8
        for (int d = 0; d < 32; d++) {
            float4 q4 = sq4[(w << 5) + d];
            const float* kr = &kT[d * 260];
            #pragma unroll
            for (int tt = 0; tt < 8; tt++) {
                float kvv = kr[(tt << 5) + lane];
                s0[tt] += q4.x * kvv;
                s1[tt] += q4.y * kvv;
                s2[tt] += q4.z * kvv;
                s3[tt] += q4.w * kvv;
            }
        }

        float inv0 = softmax_row(s0);
        float inv1 = softmax_row(s1);
        float inv2 = softmax_row(s2);
        float inv3 = softmax_row(s3);

        // store unnormalized probs as float4 per j (contiguous STS.128)
        #pragma unroll
        for (int tt = 0; tt < 8; tt++)
            pr4[(w << 8) + (tt << 5) + lane] = make_float4(s0[tt], s1[tt], s2[tt], s3[tt]);
        __syncwarp();

        // out[d] accumulation; lane = d
        float a0 = 0.f, a1 = 0.f, a2 = 0.f, a3 = 0.f;
        const int d = lane;
        #pragma unroll 4
        for (int j = 0; j < 256; j++) {
            float4 p = pr4[(w << 8) + j];
            float vvv = sv[j * 33 + d];
            a0 += p.x * vvv; a1 += p.y * vvv; a2 += p.z * vvv; a3 += p.w * vvv;
        }
        float vm = vmean[d];
        float* op = &g_att[((size_t)b * 256 + r0) * 256 + h * 32 + d];
        op[0]   = a0 * inv0 + vm;
        op[256] = a1 * inv1 + vm;
        op[512] = a2 * inv2 + vm;
        op[768] = a3 * inv3 + vm;
        __syncwarp();
    }
}

// ---------------- kernel 5: proj GEMM [131072,256] x [256,256] + bias ------
__global__ __launch_bounds__(256) void gemm_proj_kernel(
    const float* __restrict__ W, const float* __restrict__ pb,
    float* __restrict__ out) {
    __shared__ float As[16][65];
    __shared__ float Bs[16][64];
    const float* A = g_att;
    const int t = threadIdx.x;
    const int tx = t & 15, ty = t >> 4;
    const int m0 = blockIdx.y << 6, c0 = blockIdx.x << 6;
    const int la_row = t >> 2, la_k = (t & 3) << 2;
    const int lb_k = t >> 4, lb_c = (t & 15) << 2;

    unsigned long long acc[4][2];
    #pragma unroll
    for (int i = 0; i < 4; i++) { acc[i][0] = 0ULL; acc[i][1] = 0ULL; }

    for (int k0 = 0; k0 < 256; k0 += 16) {
        float4 a  = *(const float4*)&A[(size_t)(m0 + la_row) * 256 + k0 + la_k];
        float4 bb = *(const float4*)&W[(size_t)(k0 + lb_k) * 256 + c0 + lb_c];
        As[la_k + 0][la_row] = a.x; As[la_k + 1][la_row] = a.y;
        As[la_k + 2][la_row] = a.z; As[la_k + 3][la_row] = a.w;
        *(float4*)&Bs[lb_k][lb_c] = bb;
        __syncthreads();
        #pragma unroll
        for (int k = 0; k < 16; k++) {
            float4 b4 = *(const float4*)&Bs[k][tx << 2];
            unsigned long long b01 = pk2(b4.x, b4.y);
            unsigned long long b23 = pk2(b4.z, b4.w);
            #pragma unroll
            for (int i = 0; i < 4; i++) {
                float av = As[k][(ty << 2) + i];
                unsigned long long aa = pk2(av, av);
                fma2(acc[i][0], aa, b01);
                fma2(acc[i][1], aa, b23);
            }
        }
        __syncthreads();
    }

    #pragma unroll
    for (int i = 0; i < 4; i++) {
        int row = m0 + (ty << 2) + i;
        float2 v01 = up2(acc[i][0]), v23 = up2(acc[i][1]);
        float vals[4] = {v01.x, v01.y, v23.x, v23.y};
        #pragma unroll
        for (int j = 0; j < 4; j++) {
            int c = c0 + (tx << 2) + j;
            out[(size_t)row * 256 + c] = vals[j] + pb[c];
        }
    }
}

// ---------------- launch ----------------------------------------------------
extern "C" void kernel_launch(void* const* d_in, const int* in_sizes, int n_in,
                              void* d_out, int out_size) {
    const float* x             = (const float*)d_in[0];
    const float* qkv_w         = (const float*)d_in[1];
    const float* qkv_b         = (const float*)d_in[2];
    const float* proj_w        = (const float*)d_in[3];
    const float* proj_b        = (const float*)d_in[4];
    const float* logit_scale   = (const float*)d_in[5];
    const float* val_res_scale = (const float*)d_in[6];
    const float* mlp1_w        = (const float*)d_in[7];
    const float* mlp1_b        = (const float*)d_in[8];
    const float* mlp2_w        = (const float*)d_in[9];
    const float* bias_scale    = (const float*)d_in[10];
    float* out = (float*)d_out;

    cudaFuncSetAttribute(attn_kernel, cudaFuncAttributeMaxDynamicSharedMemorySize,
                         ATTN_SMEM_BYTES);

    bias_mlp_kernel<<<256, 128>>>(mlp1_w, mlp1_b, mlp2_w, bias_scale);
    bias_outer_kernel<<<2048, 256>>>();
    gemm_qkv_kernel<<<dim3(12, 2048), 256>>>(x, qkv_w, qkv_b, logit_scale);
    attn_kernel<<<4096, 256, ATTN_SMEM_BYTES>>>(val_res_scale);
    gemm_proj_kernel<<<dim3(4, 2048), 256>>>(proj_w, proj_b, out);
}

// round 5
// speedup vs baseline: 1.5818x; 1.5818x over previous
#include <cuda_runtime.h>
#include <cuda_bf16.h>
#include <math.h>
#include <stdint.h>

#define BDIM 512
#define NTOK 256
#define HNUM 8
#define HD   32

// ---------------- scratch (device globals; referenced ONLY in device code) --
__device__ __align__(256) float g_bq[HNUM * NTOK * 32];
__device__ __align__(256) float g_bk[HNUM * NTOK * 32];
__device__ __align__(256) float g_bias[HNUM * NTOK * NTOK];          // 2 MB
__device__ __align__(256) float g_q[BDIM * HNUM * NTOK * HD];        // 134 MB
__device__ __align__(256) float g_k[BDIM * HNUM * NTOK * HD];
__device__ __align__(256) float g_v[BDIM * HNUM * NTOK * HD];
__device__ __align__(256) float g_att[BDIM * NTOK * 256];            // 134 MB
__device__ __align__(256) __nv_bfloat16 g_wqkv_hi[768 * 256];
__device__ __align__(256) __nv_bfloat16 g_wqkv_lo[768 * 256];
__device__ __align__(256) __nv_bfloat16 g_wp_hi[256 * 256];
__device__ __align__(256) __nv_bfloat16 g_wp_lo[256 * 256];

// ---------------- helpers ----------------------------------------------------
__device__ __forceinline__ uint32_t smem_u32(const void* p) {
    uint32_t a;
    asm("{ .reg .u64 t; cvta.to.shared.u64 t, %1; cvt.u32.u64 %0, t; }" : "=r"(a) : "l"(p));
    return a;
}
// pack two fp32 (x -> low half, y -> high half)
__device__ __forceinline__ uint32_t packbf(float x, float y) {
    uint32_t r;
    asm("cvt.rn.bf16x2.f32 %0, %1, %2;" : "=r"(r) : "f"(y), "f"(x));
    return r;
}
__device__ __forceinline__ void split2(float x, float y, uint32_t& hi, uint32_t& lo) {
    hi = packbf(x, y);
    float hx = __uint_as_float(hi << 16);
    float hy = __uint_as_float(hi & 0xffff0000u);
    lo = packbf(x - hx, y - hy);
}
__device__ __forceinline__ void ldsm4(uint32_t (&r)[4], uint32_t a) {
    asm volatile("ldmatrix.sync.aligned.m8n8.x4.shared.b16 {%0,%1,%2,%3}, [%4];"
        : "=r"(r[0]), "=r"(r[1]), "=r"(r[2]), "=r"(r[3]) : "r"(a));
}
__device__ __forceinline__ void mma16816(float4& c, const uint32_t (&a)[4],
                                         uint32_t b0, uint32_t b1) {
    asm volatile("mma.sync.aligned.m16n8k16.row.col.f32.bf16.bf16.f32 "
        "{%0,%1,%2,%3}, {%4,%5,%6,%7}, {%8,%9}, {%0,%1,%2,%3};"
        : "+f"(c.x), "+f"(c.y), "+f"(c.z), "+f"(c.w)
        : "r"(a[0]), "r"(a[1]), "r"(a[2]), "r"(a[3]), "r"(b0), "r"(b1));
}

// ---------------- kernel 0: weight transpose + bf16 split -------------------
__global__ __launch_bounds__(256) void prep_w_kernel(
    const float* __restrict__ qkv_w, const float* __restrict__ proj_w) {
    int idx = blockIdx.x * 256 + threadIdx.x;
    if (idx < 196608) {
        int n = idx >> 8, k = idx & 255;
        float v = qkv_w[k * 768 + n];
        __nv_bfloat16 h = __float2bfloat16(v);
        g_wqkv_hi[idx] = h;
        g_wqkv_lo[idx] = __float2bfloat16(v - __bfloat162float(h));
    } else {
        int j = idx - 196608;
        int n = j >> 8, k = j & 255;
        float v = proj_w[k * 256 + n];
        __nv_bfloat16 h = __float2bfloat16(v);
        g_wp_hi[j] = h;
        g_wp_lo[j] = __float2bfloat16(v - __bfloat162float(h));
    }
}

// ---------------- kernel 1: MLP -> bq, bk (fp32) ----------------------------
__global__ __launch_bounds__(128) void bias_mlp_kernel(
    const float* __restrict__ m1w, const float* __restrict__ m1b,
    const float* __restrict__ m2w, const float* __restrict__ bs) {
    __shared__ float hf[128];
    const int n = blockIdx.x;
    const int t = threadIdx.x;
    const float invden = 1.0f / log1pf(15.0f);
    const float cy = log1pf((float)(n >> 4)) * invden;
    const float cx = log1pf((float)(n & 15)) * invden;
    {
        float z = cy * m1w[t] + cx * m1w[128 + t] + m1b[t];
        hf[t] = 0.5f * z * (1.0f + erff(z * 0.70710678118654752f));
    }
    __syncthreads();
    const float bscale = bs[0];
    for (int c = t; c < 512; c += 128) {
        float acc = 0.0f;
        #pragma unroll 8
        for (int j = 0; j < 128; j++) acc += hf[j] * m2w[j * 512 + c];
        float sig = 1.0f / (1.0f + __expf(-acc));
        int h = c >> 6, s = (c >> 5) & 1, r = c & 31;
        if (s == 0) g_bq[(h * NTOK + n) * 32 + r] = bscale * sig;
        else        g_bk[(h * NTOK + n) * 32 + r] = sig;
    }
}

// ---------------- kernel 2: bias outer product ------------------------------
__global__ __launch_bounds__(256) void bias_outer_kernel() {
    const int hn = blockIdx.x;
    const int h = hn >> 8, n = hn & 255;
    __shared__ float q[32];
    const int t = threadIdx.x;
    if (t < 32) q[t] = g_bq[(h * NTOK + n) * 32 + t];
    __syncthreads();
    const float* bkrow = &g_bk[h * (NTOK * 32) + t * 32];
    float acc = 0.0f;
    #pragma unroll
    for (int r = 0; r < 32; r++) acc += q[r] * bkrow[r];
    g_bias[h * (NTOK * NTOK) + n * NTOK + t] = acc;
}

// ---------------- GEMM via mma.sync: C[M,256] = A[M,256] * W^T --------------
// 8 warps, each m16 x n256; K staged in 32-chunks (B in smem, A direct+split).
// 3-term bf16 split: AhBh + AlBh + AhBl. fp32 epilogue.
// All device-global arrays referenced in DEVICE code (template-selected).
#define GEMM_SMEM_BYTES (2 * 256 * 80)

template <bool QKV>
__global__ __launch_bounds__(256) void gemm_mma_kernel(
    const float* __restrict__ Ain, const float* __restrict__ bias,
    const float* __restrict__ ls, float* __restrict__ outp) {
    extern __shared__ char sm[];
    char* sbh = sm;
    char* sbl = sm + 256 * 80;
    const uint32_t sbh_u = smem_u32(sbh), sbl_u = smem_u32(sbl);
    const int t = threadIdx.x, w = t >> 5, lane = t & 31;
    const int m0 = blockIdx.y * 128 + w * 16;
    const int c0 = QKV ? blockIdx.x * 256 : 0;
    const int r = lane >> 2, cc = (lane & 3) * 2;
    const int lrow = (lane & 7) + ((lane >> 4) << 3);
    const int lcol2 = (((lane >> 3) & 1) << 3) * 2;     // bytes

    // device-side selection of globals (host must NOT pass __device__ symbols)
    const float* A = QKV ? Ain : (const float*)g_att;
    const __nv_bfloat16* Bh = QKV ? g_wqkv_hi : g_wp_hi;
    const __nv_bfloat16* Bl = QKV ? g_wqkv_lo : g_wp_lo;

    float4 acc[32];
    #pragma unroll
    for (int i = 0; i < 32; i++) acc[i] = make_float4(0.f, 0.f, 0.f, 0.f);

    const float* ar0 = A + (size_t)(m0 + r) * 256;
    const float* ar8 = ar0 + 8 * 256;

    for (int kc = 0; kc < 8; kc++) {
        if (kc) __syncthreads();
        {   // stage B chunk [256 n][32 k] hi/lo, row stride 40 bf16 (80 B)
            size_t gb = (size_t)(c0 + t) * 256 + kc * 32;
            #pragma unroll
            for (int u = 0; u < 4; u++) {
                *(uint4*)(sbh + t * 80 + u * 16) = *(const uint4*)(Bh + gb + u * 8);
                *(uint4*)(sbl + t * 80 + u * 16) = *(const uint4*)(Bl + gb + u * 8);
            }
        }
        // A fragments (direct global fp32 -> bf16 hi/lo split)
        uint32_t ah[2][4], al[2][4];
        #pragma unroll
        for (int kk = 0; kk < 2; kk++) {
            int k0 = kc * 32 + kk * 16 + cc;
            float2 v0 = *(const float2*)(ar0 + k0);
            float2 v1 = *(const float2*)(ar8 + k0);
            float2 v2 = *(const float2*)(ar0 + k0 + 8);
            float2 v3 = *(const float2*)(ar8 + k0 + 8);
            split2(v0.x, v0.y, ah[kk][0], al[kk][0]);
            split2(v1.x, v1.y, ah[kk][1], al[kk][1]);
            split2(v2.x, v2.y, ah[kk][2], al[kk][2]);
            split2(v3.x, v3.y, ah[kk][3], al[kk][3]);
        }
        __syncthreads();
        #pragma unroll
        for (int n16 = 0; n16 < 16; n16++) {
            uint32_t off = (uint32_t)((n16 * 16 + lrow) * 80) + lcol2;
            uint32_t rh0[4], rh1[4], rl0[4], rl1[4];
            ldsm4(rh0, sbh_u + off);
            ldsm4(rh1, sbh_u + off + 32);
            ldsm4(rl0, sbl_u + off);
            ldsm4(rl1, sbl_u + off + 32);
            float4& cA = acc[2 * n16];
            float4& cB = acc[2 * n16 + 1];
            mma16816(cA, ah[0], rh0[0], rh0[1]); mma16816(cA, ah[1], rh1[0], rh1[1]);
            mma16816(cA, al[0], rh0[0], rh0[1]); mma16816(cA, al[1], rh1[0], rh1[1]);
            mma16816(cA, ah[0], rl0[0], rl0[1]); mma16816(cA, ah[1], rl1[0], rl1[1]);
            mma16816(cB, ah[0], rh0[2], rh0[3]); mma16816(cB, ah[1], rh1[2], rh1[3]);
            mma16816(cB, al[0], rh0[2], rh0[3]); mma16816(cB, al[1], rh1[2], rh1[3]);
            mma16816(cB, ah[0], rl0[2], rl0[3]); mma16816(cB, ah[1], rl1[2], rl1[3]);
        }
    }

    // epilogue (fp32 outputs)
    const int mrow0 = m0 + r;
    if (QKV) {
        const int s = blockIdx.x;
        float* dst = (s == 0) ? g_q : (s == 1 ? g_k : g_v);
        const int bidx = mrow0 >> 8, n0r = mrow0 & 255, n1r = n0r + 8;
        #pragma unroll
        for (int ti = 0; ti < 32; ti++) {
            int c = ti * 8 + cc;
            float2 bb = *(const float2*)(bias + c0 + c);
            float scv = (s == 0) ? __ldg(ls + (c >> 5)) : 1.0f;
            int h = c >> 5, d = c & 31;
            size_t i0 = ((size_t)(bidx * 8 + h) * 256 + n0r) * 32 + d;
            size_t i1 = ((size_t)(bidx * 8 + h) * 256 + n1r) * 32 + d;
            *(float2*)(dst + i0) = make_float2((acc[ti].x + bb.x) * scv,
                                               (acc[ti].y + bb.y) * scv);
            *(float2*)(dst + i1) = make_float2((acc[ti].z + bb.x) * scv,
                                               (acc[ti].w + bb.y) * scv);
        }
    } else {
        #pragma unroll
        for (int ti = 0; ti < 32; ti++) {
            int c = ti * 8 + cc;
            float2 bb = *(const float2*)(bias + c);
            *(float2*)(outp + (size_t)mrow0 * 256 + c) =
                make_float2(acc[ti].x + bb.x, acc[ti].y + bb.y);
            *(float2*)(outp + (size_t)(mrow0 + 8) * 256 + c) =
                make_float2(acc[ti].z + bb.x, acc[ti].w + bb.y);
        }
    }
}

// ---------------- kernel 4: attention per (b,h) (R1-validated, SIMT) --------
#define ATTN_SMEM_FLOATS (32 * 260 + 256 * 33 + 8 * 256 * 4 + 8 * 32 * 4 + 32 + 256)
#define ATTN_SMEM_BYTES  (ATTN_SMEM_FLOATS * 4)

__device__ __forceinline__ float softmax_row(float* s) {
    float m = s[0];
    #pragma unroll
    for (int i = 1; i < 8; i++) m = fmaxf(m, s[i]);
    #pragma unroll
    for (int o = 16; o > 0; o >>= 1) m = fmaxf(m, __shfl_xor_sync(0xffffffffu, m, o));
    float sum = 0.0f;
    #pragma unroll
    for (int i = 0; i < 8; i++) { s[i] = __expf(s[i] - m); sum += s[i]; }
    #pragma unroll
    for (int o = 16; o > 0; o >>= 1) sum += __shfl_xor_sync(0xffffffffu, sum, o);
    return 1.0f / sum;
}

__global__ __launch_bounds__(256) void attn_kernel(const float* __restrict__ vrs) {
    extern __shared__ float smf[];
    float* kT    = smf;
    float* sv    = kT + 32 * 260;
    float* pr    = sv + 256 * 33;
    float* sq    = pr + 8 * 256 * 4;
    float* vmean = sq + 8 * 32 * 4;
    float* part  = vmean + 32;

    const int bh = blockIdx.x;
    const int b = bh >> 3, h = bh & 7;
    const float* qp = g_q + (size_t)bh * (NTOK * HD);
    const float* kp = g_k + (size_t)bh * (NTOK * HD);
    const float* vp = g_v + (size_t)bh * (NTOK * HD);
    const float* bp = g_bias + h * (NTOK * NTOK);
    const int t = threadIdx.x, w = t >> 5, lane = t & 31;

    for (int i = t; i < 2048; i += 256) {
        float4 kk = ((const float4*)kp)[i];
        float4 vv = ((const float4*)vp)[i];
        int n = i >> 3, d = (i & 7) << 2;
        kT[(d + 0) * 260 + n] = kk.x; kT[(d + 1) * 260 + n] = kk.y;
        kT[(d + 2) * 260 + n] = kk.z; kT[(d + 3) * 260 + n] = kk.w;
        sv[n * 33 + d + 0] = vv.x; sv[n * 33 + d + 1] = vv.y;
        sv[n * 33 + d + 2] = vv.z; sv[n * 33 + d + 3] = vv.w;
    }
    __syncthreads();

    {
        float s = 0.0f;
        int base = w << 5;
        #pragma unroll
        for (int r = 0; r < 32; r++) s += sv[(base + r) * 33 + lane];
        part[(w << 5) + lane] = s;
    }
    __syncthreads();
    if (t < 32) {
        float s = 0.0f;
        #pragma unroll
        for (int g = 0; g < 8; g++) s += part[(g << 5) + t];
        vmean[t] = s * (1.0f / 256.0f) * vrs[h];
    }
    __syncthreads();

    float4* sq4 = (float4*)sq;
    float4* pr4 = (float4*)pr;

    for (int pass = 0; pass < 8; pass++) {
        const int r0 = (pass << 5) + (w << 2);

        float4 qv;
        qv.x = qp[(r0 + 0) * 32 + lane];
        qv.y = qp[(r0 + 1) * 32 + lane];
        qv.z = qp[(r0 + 2) * 32 + lane];
        qv.w = qp[(r0 + 3) * 32 + lane];
        sq4[(w << 5) + lane] = qv;
        __syncwarp();

        float s0[8], s1[8], s2[8], s3[8];
        #pragma unroll
        for (int tt = 0; tt < 8; tt++) {
            int j = (tt << 5) + lane;
            s0[tt] = bp[(r0 + 0) * 256 + j];
            s1[tt] = bp[(r0 + 1) * 256 + j];
            s2[tt] = bp[(r0 + 2) * 256 + j];
            s3[tt] = bp[(r0 + 3) * 256 + j];
        }
        #pragma unroll 8
        for (int d = 0; d < 32; d++) {
            float4 q4 = sq4[(w << 5) + d];
            const float* kr = &kT[d * 260];
            #pragma unroll
            for (int tt = 0; tt < 8; tt++) {
                float kvv = kr[(tt << 5) + lane];
                s0[tt] += q4.x * kvv;
                s1[tt] += q4.y * kvv;
                s2[tt] += q4.z * kvv;
                s3[tt] += q4.w * kvv;
            }
        }

        float inv0 = softmax_row(s0);
        float inv1 = softmax_row(s1);
        float inv2 = softmax_row(s2);
        float inv3 = softmax_row(s3);

        #pragma unroll
        for (int tt = 0; tt < 8; tt++)
            pr4[(w << 8) + (tt << 5) + lane] = make_float4(s0[tt], s1[tt], s2[tt], s3[tt]);
        __syncwarp();

        float a0 = 0.f, a1 = 0.f, a2 = 0.f, a3 = 0.f;
        const int d = lane;
        #pragma unroll 4
        for (int j = 0; j < 256; j++) {
            float4 p = pr4[(w << 8) + j];
            float vvv = sv[j * 33 + d];
            a0 += p.x * vvv; a1 += p.y * vvv; a2 += p.z * vvv; a3 += p.w * vvv;
        }
        float vm = vmean[d];
        float* op = &g_att[((size_t)b * 256 + r0) * 256 + h * 32 + d];
        op[0]   = a0 * inv0 + vm;
        op[256] = a1 * inv1 + vm;
        op[512] = a2 * inv2 + vm;
        op[768] = a3 * inv3 + vm;
        __syncwarp();
    }
}

// ---------------- launch -----------------------------------------------------
extern "C" void kernel_launch(void* const* d_in, const int* in_sizes, int n_in,
                              void* d_out, int out_size) {
    const float* x             = (const float*)d_in[0];
    const float* qkv_w         = (const float*)d_in[1];
    const float* qkv_b         = (const float*)d_in[2];
    const float* proj_w        = (const float*)d_in[3];
    const float* proj_b        = (const float*)d_in[4];
    const float* logit_scale   = (const float*)d_in[5];
    const float* val_res_scale = (const float*)d_in[6];
    const float* mlp1_w        = (const float*)d_in[7];
    const float* mlp1_b        = (const float*)d_in[8];
    const float* mlp2_w        = (const float*)d_in[9];
    const float* bias_scale    = (const float*)d_in[10];
    float* out = (float*)d_out;

    cudaFuncSetAttribute(attn_kernel, cudaFuncAttributeMaxDynamicSharedMemorySize,
                         ATTN_SMEM_BYTES);
    cudaFuncSetAttribute(gemm_mma_kernel<true>, cudaFuncAttributeMaxDynamicSharedMemorySize,
                         GEMM_SMEM_BYTES);
    cudaFuncSetAttribute(gemm_mma_kernel<false>, cudaFuncAttributeMaxDynamicSharedMemorySize,
                         GEMM_SMEM_BYTES);

    prep_w_kernel<<<1024, 256>>>(qkv_w, proj_w);
    bias_mlp_kernel<<<256, 128>>>(mlp1_w, mlp1_b, mlp2_w, bias_scale);
    bias_outer_kernel<<<2048, 256>>>();
    gemm_mma_kernel<true><<<dim3(3, 1024), 256, GEMM_SMEM_BYTES>>>(
        x, qkv_b, logit_scale, nullptr);
    attn_kernel<<<4096, 256, ATTN_SMEM_BYTES>>>(val_res_scale);
    gemm_mma_kernel<false><<<dim3(1, 1024), 256, GEMM_SMEM_BYTES>>>(
        x /*unused*/, proj_b, nullptr, out);
}

// round 6
// speedup vs baseline: 2.3866x; 1.5088x over previous
#include <cuda_runtime.h>
#include <cuda_bf16.h>
#include <math.h>
#include <stdint.h>

#define BDIM 512
#define NTOK 256
#define HNUM 8
#define HD   32

// ---------------- scratch (device globals; referenced ONLY in device code) --
__device__ __align__(256) __nv_bfloat16 g_qh[BDIM*HNUM*NTOK*HD];
__device__ __align__(256) __nv_bfloat16 g_ql[BDIM*HNUM*NTOK*HD];
__device__ __align__(256) __nv_bfloat16 g_kh[BDIM*HNUM*NTOK*HD];
__device__ __align__(256) __nv_bfloat16 g_kl[BDIM*HNUM*NTOK*HD];
__device__ __align__(256) __nv_bfloat16 g_vh[BDIM*HNUM*NTOK*HD];
__device__ __align__(256) __nv_bfloat16 g_vl[BDIM*HNUM*NTOK*HD];
__device__ __align__(256) float g_att[BDIM*NTOK*256];                // 134 MB
__device__ __align__(256) __nv_bfloat16 g_wqkv_hi[768*256];
__device__ __align__(256) __nv_bfloat16 g_wqkv_lo[768*256];
__device__ __align__(256) __nv_bfloat16 g_wp_hi[256*256];
__device__ __align__(256) __nv_bfloat16 g_wp_lo[256*256];
__device__ __align__(256) __nv_bfloat16 g_bqh[HNUM*NTOK*HD];
__device__ __align__(256) __nv_bfloat16 g_bql[HNUM*NTOK*HD];
__device__ __align__(256) __nv_bfloat16 g_bkh[HNUM*NTOK*HD];
__device__ __align__(256) __nv_bfloat16 g_bkl[HNUM*NTOK*HD];

// ---------------- helpers ----------------------------------------------------
__device__ __forceinline__ uint32_t smem_u32(const void* p) {
    uint32_t a;
    asm("{ .reg .u64 t; cvta.to.shared.u64 t, %1; cvt.u32.u64 %0, t; }" : "=r"(a) : "l"(p));
    return a;
}
// pack two fp32 (x -> low half, y -> high half)
__device__ __forceinline__ uint32_t packbf(float x, float y) {
    uint32_t r;
    asm("cvt.rn.bf16x2.f32 %0, %1, %2;" : "=r"(r) : "f"(y), "f"(x));
    return r;
}
__device__ __forceinline__ void split2(float x, float y, uint32_t& hi, uint32_t& lo) {
    hi = packbf(x, y);
    float hx = __uint_as_float(hi << 16);
    float hy = __uint_as_float(hi & 0xffff0000u);
    lo = packbf(x - hx, y - hy);
}
__device__ __forceinline__ void ldsm4(uint32_t (&r)[4], uint32_t a) {
    asm volatile("ldmatrix.sync.aligned.m8n8.x4.shared.b16 {%0,%1,%2,%3}, [%4];"
        : "=r"(r[0]), "=r"(r[1]), "=r"(r[2]), "=r"(r[3]) : "r"(a));
}
__device__ __forceinline__ void ldsm4t(uint32_t (&r)[4], uint32_t a) {
    asm volatile("ldmatrix.sync.aligned.m8n8.x4.trans.shared.b16 {%0,%1,%2,%3}, [%4];"
        : "=r"(r[0]), "=r"(r[1]), "=r"(r[2]), "=r"(r[3]) : "r"(a));
}
__device__ __forceinline__ void mma16816(float4& c, const uint32_t (&a)[4],
                                         uint32_t b0, uint32_t b1) {
    asm volatile("mma.sync.aligned.m16n8k16.row.col.f32.bf16.bf16.f32 "
        "{%0,%1,%2,%3}, {%4,%5,%6,%7}, {%8,%9}, {%0,%1,%2,%3};"
        : "+f"(c.x), "+f"(c.y), "+f"(c.z), "+f"(c.w)
        : "r"(a[0]), "r"(a[1]), "r"(a[2]), "r"(a[3]), "r"(b0), "r"(b1));
}

// ---------------- kernel 0: weight transpose + bf16 split -------------------
__global__ __launch_bounds__(256) void prep_w_kernel(
    const float* __restrict__ qkv_w, const float* __restrict__ proj_w) {
    int idx = blockIdx.x * 256 + threadIdx.x;
    if (idx < 196608) {
        int n = idx >> 8, k = idx & 255;
        float v = qkv_w[k * 768 + n];
        __nv_bfloat16 h = __float2bfloat16(v);
        g_wqkv_hi[idx] = h;
        g_wqkv_lo[idx] = __float2bfloat16(v - __bfloat162float(h));
    } else {
        int j = idx - 196608;
        int n = j >> 8, k = j & 255;
        float v = proj_w[k * 256 + n];
        __nv_bfloat16 h = __float2bfloat16(v);
        g_wp_hi[j] = h;
        g_wp_lo[j] = __float2bfloat16(v - __bfloat162float(h));
    }
}

// ---------------- kernel 1: MLP -> bq, bk (bf16 hi/lo) ----------------------
__global__ __launch_bounds__(128) void bias_mlp_kernel(
    const float* __restrict__ m1w, const float* __restrict__ m1b,
    const float* __restrict__ m2w, const float* __restrict__ bs) {
    __shared__ float hf[128];
    const int n = blockIdx.x;
    const int t = threadIdx.x;
    const float invden = 1.0f / log1pf(15.0f);
    const float cy = log1pf((float)(n >> 4)) * invden;
    const float cx = log1pf((float)(n & 15)) * invden;
    {
        float z = cy * m1w[t] + cx * m1w[128 + t] + m1b[t];
        hf[t] = 0.5f * z * (1.0f + erff(z * 0.70710678118654752f));
    }
    __syncthreads();
    const float bscale = bs[0];
    for (int c = t; c < 512; c += 128) {
        float acc = 0.0f;
        #pragma unroll 8
        for (int j = 0; j < 128; j++) acc += hf[j] * m2w[j * 512 + c];
        float sig = 1.0f / (1.0f + __expf(-acc));
        int h = c >> 6, s = (c >> 5) & 1, r = c & 31;
        float v = (s == 0) ? bscale * sig : sig;
        __nv_bfloat16 vh = __float2bfloat16(v);
        __nv_bfloat16 vl = __float2bfloat16(v - __bfloat162float(vh));
        int idx = (h * NTOK + n) * 32 + r;
        if (s == 0) { g_bqh[idx] = vh; g_bql[idx] = vl; }
        else        { g_bkh[idx] = vh; g_bkl[idx] = vl; }
    }
}

// ---------------- GEMM via mma.sync (validated core) ------------------------
#define GEMM_SMEM_BYTES (2 * 256 * 80)

template <bool QKV>
__global__ __launch_bounds__(256) void gemm_mma_kernel(
    const float* __restrict__ Ain, const float* __restrict__ bias,
    const float* __restrict__ ls, float* __restrict__ outp) {
    extern __shared__ char sm[];
    char* sbh = sm;
    char* sbl = sm + 256 * 80;
    const uint32_t sbh_u = smem_u32(sbh), sbl_u = smem_u32(sbl);
    const int t = threadIdx.x, w = t >> 5, lane = t & 31;
    const int m0 = blockIdx.y * 128 + w * 16;
    const int c0 = QKV ? blockIdx.x * 256 : 0;
    const int r = lane >> 2, cc = (lane & 3) * 2;
    const int lrow = (lane & 7) + ((lane >> 4) << 3);
    const int lcol2 = (((lane >> 3) & 1) << 3) * 2;

    const float* A = QKV ? Ain : (const float*)g_att;
    const __nv_bfloat16* Bh = QKV ? g_wqkv_hi : g_wp_hi;
    const __nv_bfloat16* Bl = QKV ? g_wqkv_lo : g_wp_lo;

    float4 acc[32];
    #pragma unroll
    for (int i = 0; i < 32; i++) acc[i] = make_float4(0.f, 0.f, 0.f, 0.f);

    const float* ar0 = A + (size_t)(m0 + r) * 256;
    const float* ar8 = ar0 + 8 * 256;

    for (int kc = 0; kc < 8; kc++) {
        if (kc) __syncthreads();
        {
            size_t gb = (size_t)(c0 + t) * 256 + kc * 32;
            #pragma unroll
            for (int u = 0; u < 4; u++) {
                *(uint4*)(sbh + t * 80 + u * 16) = *(const uint4*)(Bh + gb + u * 8);
                *(uint4*)(sbl + t * 80 + u * 16) = *(const uint4*)(Bl + gb + u * 8);
            }
        }
        uint32_t ah[2][4], al[2][4];
        #pragma unroll
        for (int kk = 0; kk < 2; kk++) {
            int k0 = kc * 32 + kk * 16 + cc;
            float2 v0 = *(const float2*)(ar0 + k0);
            float2 v1 = *(const float2*)(ar8 + k0);
            float2 v2 = *(const float2*)(ar0 + k0 + 8);
            float2 v3 = *(const float2*)(ar8 + k0 + 8);
            split2(v0.x, v0.y, ah[kk][0], al[kk][0]);
            split2(v1.x, v1.y, ah[kk][1], al[kk][1]);
            split2(v2.x, v2.y, ah[kk][2], al[kk][2]);
            split2(v3.x, v3.y, ah[kk][3], al[kk][3]);
        }
        __syncthreads();
        #pragma unroll
        for (int n16 = 0; n16 < 16; n16++) {
            uint32_t off = (uint32_t)((n16 * 16 + lrow) * 80) + lcol2;
            uint32_t rh0[4], rh1[4], rl0[4], rl1[4];
            ldsm4(rh0, sbh_u + off);
            ldsm4(rh1, sbh_u + off + 32);
            ldsm4(rl0, sbl_u + off);
            ldsm4(rl1, sbl_u + off + 32);
            float4& cA = acc[2 * n16];
            float4& cB = acc[2 * n16 + 1];
            mma16816(cA, ah[0], rh0[0], rh0[1]); mma16816(cA, ah[1], rh1[0], rh1[1]);
            mma16816(cA, al[0], rh0[0], rh0[1]); mma16816(cA, al[1], rh1[0], rh1[1]);
            mma16816(cA, ah[0], rl0[0], rl0[1]); mma16816(cA, ah[1], rl1[0], rl1[1]);
            mma16816(cB, ah[0], rh0[2], rh0[3]); mma16816(cB, ah[1], rh1[2], rh1[3]);
            mma16816(cB, al[0], rh0[2], rh0[3]); mma16816(cB, al[1], rh1[2], rh1[3]);
            mma16816(cB, ah[0], rl0[2], rl0[3]); mma16816(cB, ah[1], rl1[2], rl1[3]);
        }
    }

    const int mrow0 = m0 + r;
    if (QKV) {
        const int s = blockIdx.x;
        __nv_bfloat16* dh = (s == 0) ? g_qh : (s == 1 ? g_kh : g_vh);
        __nv_bfloat16* dl = (s == 0) ? g_ql : (s == 1 ? g_kl : g_vl);
        const int bidx = mrow0 >> 8, n0r = mrow0 & 255, n1r = n0r + 8;
        #pragma unroll
        for (int ti = 0; ti < 32; ti++) {
            int c = ti * 8 + cc;
            float2 bb = *(const float2*)(bias + c0 + c);
            float scv = (s == 0) ? __ldg(ls + (c >> 5)) : 1.0f;
            float v00 = (acc[ti].x + bb.x) * scv, v01 = (acc[ti].y + bb.y) * scv;
            float v10 = (acc[ti].z + bb.x) * scv, v11 = (acc[ti].w + bb.y) * scv;
            int h = c >> 5, d = c & 31;
            size_t i0 = ((size_t)(bidx * 8 + h) * 256 + n0r) * 32 + d;
            size_t i1 = ((size_t)(bidx * 8 + h) * 256 + n1r) * 32 + d;
            uint32_t hi, lo;
            split2(v00, v01, hi, lo);
            *(uint32_t*)&dh[i0] = hi; *(uint32_t*)&dl[i0] = lo;
            split2(v10, v11, hi, lo);
            *(uint32_t*)&dh[i1] = hi; *(uint32_t*)&dl[i1] = lo;
        }
    } else {
        #pragma unroll
        for (int ti = 0; ti < 32; ti++) {
            int c = ti * 8 + cc;
            float2 bb = *(const float2*)(bias + c);
            *(float2*)(outp + (size_t)mrow0 * 256 + c) =
                make_float2(acc[ti].x + bb.x, acc[ti].y + bb.y);
            *(float2*)(outp + (size_t)(mrow0 + 8) * 256 + c) =
                make_float2(acc[ti].z + bb.x, acc[ti].w + bb.y);
        }
    }
}

// ---------------- attention kernel (per b,h), HMMA --------------------------
#define AS_KHI   0
#define AS_KLO   20480
#define AS_BKH   40960
#define AS_BKL   61440
#define AS_VHI   81920
#define AS_VLO   102400
#define AS_VMEAN 122880
#define AS_RED   123008
#define ATTN_SMEM_BYTES (123008 + 1024)

__global__ __launch_bounds__(256) void attn_mma_kernel(const float* __restrict__ vrs) {
    extern __shared__ char sm[];
    const uint32_t sb = smem_u32(sm);
    const int bh = blockIdx.x;
    const int b = bh >> 3, h = bh & 7;
    const int t = threadIdx.x, w = t >> 5, lane = t & 31;
    const int r = lane >> 2, cc = (lane & 3) * 2;
    const int lrow = (lane & 7) + ((lane >> 4) << 3);
    const int lcol2 = (((lane >> 3) & 1) << 3) * 2;
    const int lrowT = lane & 15;
    const int lcolT2 = ((lane >> 4) << 3) * 2;

    // ---- stage K, bk, V (hi/lo), 80-byte row stride ----
    {
        size_t gk = (size_t)bh * 8192 + (size_t)t * 32;
        size_t gb = (size_t)h * 8192 + (size_t)t * 32;
        #pragma unroll
        for (int u = 0; u < 4; u++) {
            *(uint4*)(sm + AS_KHI + t * 80 + u * 16) = *(const uint4*)(g_kh + gk + u * 8);
            *(uint4*)(sm + AS_KLO + t * 80 + u * 16) = *(const uint4*)(g_kl + gk + u * 8);
            *(uint4*)(sm + AS_VHI + t * 80 + u * 16) = *(const uint4*)(g_vh + gk + u * 8);
            *(uint4*)(sm + AS_VLO + t * 80 + u * 16) = *(const uint4*)(g_vl + gk + u * 8);
            *(uint4*)(sm + AS_BKH + t * 80 + u * 16) = *(const uint4*)(g_bkh + gb + u * 8);
            *(uint4*)(sm + AS_BKL + t * 80 + u * 16) = *(const uint4*)(g_bkl + gb + u * 8);
        }
    }
    __syncthreads();

    // ---- vmean (pre-scaled by val_res_scale[h]) ----
    {
        int d = t & 31, grp = t >> 5;
        float s = 0.0f;
        for (int n = grp * 32; n < grp * 32 + 32; n++) {
            uint16_t hv = *(const uint16_t*)(sm + AS_VHI + n * 80 + d * 2);
            uint16_t lv = *(const uint16_t*)(sm + AS_VLO + n * 80 + d * 2);
            s += __uint_as_float(((uint32_t)hv) << 16) + __uint_as_float(((uint32_t)lv) << 16);
        }
        ((float*)(sm + AS_RED))[grp * 32 + d] = s;
    }
    __syncthreads();
    if (t < 32) {
        float s = 0.0f;
        #pragma unroll
        for (int g = 0; g < 8; g++) s += ((float*)(sm + AS_RED))[g * 32 + t];
        ((float*)(sm + AS_VMEAN))[t] = s * (1.0f / 256.0f) * __ldg(vrs + h);
    }
    __syncthreads();

    for (int pass = 0; pass < 2; pass++) {
        const int tok0 = pass * 128 + w * 16 + r;
        // ---- load Q / bq A-fragments (direct global, bf16 pairs) ----
        uint32_t aqh[2][4], aql[2][4], abh[2][4], abl[2][4];
        {
            size_t q0 = (size_t)bh * 8192 + (size_t)tok0 * 32;
            size_t b0 = (size_t)h * 8192 + (size_t)tok0 * 32;
            #pragma unroll
            for (int kk = 0; kk < 2; kk++) {
                int o = kk * 16 + cc;
                aqh[kk][0] = *(const uint32_t*)(g_qh + q0 + o);
                aqh[kk][1] = *(const uint32_t*)(g_qh + q0 + 256 + o);
                aqh[kk][2] = *(const uint32_t*)(g_qh + q0 + o + 8);
                aqh[kk][3] = *(const uint32_t*)(g_qh + q0 + 256 + o + 8);
                aql[kk][0] = *(const uint32_t*)(g_ql + q0 + o);
                aql[kk][1] = *(const uint32_t*)(g_ql + q0 + 256 + o);
                aql[kk][2] = *(const uint32_t*)(g_ql + q0 + o + 8);
                aql[kk][3] = *(const uint32_t*)(g_ql + q0 + 256 + o + 8);
                abh[kk][0] = *(const uint32_t*)(g_bqh + b0 + o);
                abh[kk][1] = *(const uint32_t*)(g_bqh + b0 + 256 + o);
                abh[kk][2] = *(const uint32_t*)(g_bqh + b0 + o + 8);
                abh[kk][3] = *(const uint32_t*)(g_bqh + b0 + 256 + o + 8);
                abl[kk][0] = *(const uint32_t*)(g_bql + b0 + o);
                abl[kk][1] = *(const uint32_t*)(g_bql + b0 + 256 + o);
                abl[kk][2] = *(const uint32_t*)(g_bql + b0 + o + 8);
                abl[kk][3] = *(const uint32_t*)(g_bql + b0 + 256 + o + 8);
            }
        }

        // ---- S = Q K^T + bq bk^T (3-term splits) ----
        float4 sc[32];
        #pragma unroll
        for (int i = 0; i < 32; i++) sc[i] = make_float4(0.f, 0.f, 0.f, 0.f);
        #pragma unroll
        for (int n16 = 0; n16 < 16; n16++) {
            uint32_t off = (uint32_t)((n16 * 16 + lrow) * 80) + lcol2;
            uint32_t kh0[4], kh1[4], kl0[4], kl1[4];
            uint32_t bh0[4], bh1[4], bl0[4], bl1[4];
            ldsm4(kh0, sb + AS_KHI + off); ldsm4(kh1, sb + AS_KHI + off + 32);
            ldsm4(kl0, sb + AS_KLO + off); ldsm4(kl1, sb + AS_KLO + off + 32);
            ldsm4(bh0, sb + AS_BKH + off); ldsm4(bh1, sb + AS_BKH + off + 32);
            ldsm4(bl0, sb + AS_BKL + off); ldsm4(bl1, sb + AS_BKL + off + 32);
            float4& cA = sc[2 * n16];
            float4& cB = sc[2 * n16 + 1];
            mma16816(cA, aqh[0], kh0[0], kh0[1]); mma16816(cA, aqh[1], kh1[0], kh1[1]);
            mma16816(cA, aql[0], kh0[0], kh0[1]); mma16816(cA, aql[1], kh1[0], kh1[1]);
            mma16816(cA, aqh[0], kl0[0], kl0[1]); mma16816(cA, aqh[1], kl1[0], kl1[1]);
            mma16816(cA, abh[0], bh0[0], bh0[1]); mma16816(cA, abh[1], bh1[0], bh1[1]);
            mma16816(cA, abl[0], bh0[0], bh0[1]); mma16816(cA, abl[1], bh1[0], bh1[1]);
            mma16816(cA, abh[0], bl0[0], bl0[1]); mma16816(cA, abh[1], bl1[0], bl1[1]);
            mma16816(cB, aqh[0], kh0[2], kh0[3]); mma16816(cB, aqh[1], kh1[2], kh1[3]);
            mma16816(cB, aql[0], kh0[2], kh0[3]); mma16816(cB, aql[1], kh1[2], kh1[3]);
            mma16816(cB, aqh[0], kl0[2], kl0[3]); mma16816(cB, aqh[1], kl1[2], kl1[3]);
            mma16816(cB, abh[0], bh0[2], bh0[3]); mma16816(cB, abh[1], bh1[2], bh1[3]);
            mma16816(cB, abl[0], bh0[2], bh0[3]); mma16816(cB, abl[1], bh1[2], bh1[3]);
            mma16816(cB, abh[0], bl0[2], bl0[3]); mma16816(cB, abh[1], bl1[2], bl1[3]);
        }

        // ---- softmax (2 rows per thread; 4-lane groups share rows) ----
        float m0 = -1e30f, m1 = -1e30f;
        #pragma unroll
        for (int i = 0; i < 32; i++) {
            m0 = fmaxf(m0, fmaxf(sc[i].x, sc[i].y));
            m1 = fmaxf(m1, fmaxf(sc[i].z, sc[i].w));
        }
        m0 = fmaxf(m0, __shfl_xor_sync(0xffffffffu, m0, 1));
        m0 = fmaxf(m0, __shfl_xor_sync(0xffffffffu, m0, 2));
        m1 = fmaxf(m1, __shfl_xor_sync(0xffffffffu, m1, 1));
        m1 = fmaxf(m1, __shfl_xor_sync(0xffffffffu, m1, 2));
        float s0 = 0.f, s1 = 0.f;
        #pragma unroll
        for (int i = 0; i < 32; i++) {
            sc[i].x = __expf(sc[i].x - m0); sc[i].y = __expf(sc[i].y - m0);
            sc[i].z = __expf(sc[i].z - m1); sc[i].w = __expf(sc[i].w - m1);
            s0 += sc[i].x + sc[i].y; s1 += sc[i].z + sc[i].w;
        }
        s0 += __shfl_xor_sync(0xffffffffu, s0, 1);
        s0 += __shfl_xor_sync(0xffffffffu, s0, 2);
        s1 += __shfl_xor_sync(0xffffffffu, s1, 1);
        s1 += __shfl_xor_sync(0xffffffffu, s1, 2);
        float inv0 = 1.0f / s0, inv1 = 1.0f / s1;

        // ---- O = P V (P hi/lo from accum regs, V via ldmatrix.trans) ----
        float4 o[4];
        #pragma unroll
        for (int i = 0; i < 4; i++) o[i] = make_float4(0.f, 0.f, 0.f, 0.f);
        #pragma unroll
        for (int tk = 0; tk < 16; tk++) {
            uint32_t Ahi[4], Alo[4];
            split2(sc[2 * tk].x,     sc[2 * tk].y,     Ahi[0], Alo[0]);
            split2(sc[2 * tk].z,     sc[2 * tk].w,     Ahi[1], Alo[1]);
            split2(sc[2 * tk + 1].x, sc[2 * tk + 1].y, Ahi[2], Alo[2]);
            split2(sc[2 * tk + 1].z, sc[2 * tk + 1].w, Ahi[3], Alo[3]);
            uint32_t off = (uint32_t)((tk * 16 + lrowT) * 80) + lcolT2;
            uint32_t vh0[4], vh1[4], vl0[4], vl1[4];
            ldsm4t(vh0, sb + AS_VHI + off); ldsm4t(vh1, sb + AS_VHI + off + 32);
            ldsm4t(vl0, sb + AS_VLO + off); ldsm4t(vl1, sb + AS_VLO + off + 32);
            mma16816(o[0], Ahi, vh0[0], vh0[1]); mma16816(o[1], Ahi, vh0[2], vh0[3]);
            mma16816(o[2], Ahi, vh1[0], vh1[1]); mma16816(o[3], Ahi, vh1[2], vh1[3]);
            mma16816(o[0], Alo, vh0[0], vh0[1]); mma16816(o[1], Alo, vh0[2], vh0[3]);
            mma16816(o[2], Alo, vh1[0], vh1[1]); mma16816(o[3], Alo, vh1[2], vh1[3]);
            mma16816(o[0], Ahi, vl0[0], vl0[1]); mma16816(o[1], Ahi, vl0[2], vl0[3]);
            mma16816(o[2], Ahi, vl1[0], vl1[1]); mma16816(o[3], Ahi, vl1[2], vl1[3]);
        }

        // ---- write out (normalize + vmean residual) ----
        const float* vmean = (const float*)(sm + AS_VMEAN);
        float* out0 = g_att + ((size_t)b * 256 + tok0) * 256 + h * 32;
        float* out1 = out0 + 8 * 256;
        #pragma unroll
        for (int dt = 0; dt < 4; dt++) {
            int d = dt * 8 + cc;
            float vm0 = vmean[d], vm1 = vmean[d + 1];
            *(float2*)(out0 + d) = make_float2(o[dt].x * inv0 + vm0, o[dt].y * inv0 + vm1);
            *(float2*)(out1 + d) = make_float2(o[dt].z * inv1 + vm0, o[dt].w * inv1 + vm1);
        }
    }
}

// ---------------- launch -----------------------------------------------------
extern "C" void kernel_launch(void* const* d_in, const int* in_sizes, int n_in,
                              void* d_out, int out_size) {
    const float* x             = (const float*)d_in[0];
    const float* qkv_b         = (const float*)d_in[2];
    const float* proj_b        = (const float*)d_in[4];
    const float* logit_scale   = (const float*)d_in[5];
    const float* val_res_scale = (const float*)d_in[6];
    const float* mlp1_w        = (const float*)d_in[7];
    const float* mlp1_b        = (const float*)d_in[8];
    const float* mlp2_w        = (const float*)d_in[9];
    const float* bias_scale    = (const float*)d_in[10];
    const float* qkv_w         = (const float*)d_in[1];
    const float* proj_w        = (const float*)d_in[3];
    float* out = (float*)d_out;

    cudaFuncSetAttribute(attn_mma_kernel, cudaFuncAttributeMaxDynamicSharedMemorySize,
                         ATTN_SMEM_BYTES);
    cudaFuncSetAttribute(gemm_mma_kernel<true>, cudaFuncAttributeMaxDynamicSharedMemorySize,
                         GEMM_SMEM_BYTES);
    cudaFuncSetAttribute(gemm_mma_kernel<false>, cudaFuncAttributeMaxDynamicSharedMemorySize,
                         GEMM_SMEM_BYTES);

    prep_w_kernel<<<1024, 256>>>(qkv_w, proj_w);
    bias_mlp_kernel<<<256, 128>>>(mlp1_w, mlp1_b, mlp2_w, bias_scale);
    gemm_mma_kernel<true><<<dim3(3, 1024), 256, GEMM_SMEM_BYTES>>>(
        x, qkv_b, logit_scale, nullptr);
    attn_mma_kernel<<<4096, 256, ATTN_SMEM_BYTES>>>(val_res_scale);
    gemm_mma_kernel<false><<<dim3(1, 1024), 256, GEMM_SMEM_BYTES>>>(
        x /*unused*/, proj_b, nullptr, out);
}

// round 7
// speedup vs baseline: 2.5767x; 1.0797x over previous
#include <cuda_runtime.h>
#include <cuda_bf16.h>
#include <math.h>
#include <stdint.h>

#define BDIM 512
#define NTOK 256
#define HNUM 8
#define HD   32

// ---------------- scratch (device globals; referenced ONLY in device code) --
__device__ __align__(256) __nv_bfloat16 g_qh[BDIM*HNUM*NTOK*HD];
__device__ __align__(256) __nv_bfloat16 g_ql[BDIM*HNUM*NTOK*HD];
__device__ __align__(256) __nv_bfloat16 g_kh[BDIM*HNUM*NTOK*HD];
__device__ __align__(256) __nv_bfloat16 g_kl[BDIM*HNUM*NTOK*HD];
__device__ __align__(256) __nv_bfloat16 g_vh[BDIM*HNUM*NTOK*HD];
__device__ __align__(256) __nv_bfloat16 g_vl[BDIM*HNUM*NTOK*HD];
__device__ __align__(256) float g_att[BDIM*NTOK*256];                // 134 MB
__device__ __align__(256) __nv_bfloat16 g_wqkv_hi[768*256];
__device__ __align__(256) __nv_bfloat16 g_wqkv_lo[768*256];
__device__ __align__(256) __nv_bfloat16 g_wp_hi[256*256];
__device__ __align__(256) __nv_bfloat16 g_wp_lo[256*256];
__device__ __align__(256) __nv_bfloat16 g_bqh[HNUM*NTOK*HD];
__device__ __align__(256) __nv_bfloat16 g_bql[HNUM*NTOK*HD];
__device__ __align__(256) __nv_bfloat16 g_bkh[HNUM*NTOK*HD];
__device__ __align__(256) __nv_bfloat16 g_bkl[HNUM*NTOK*HD];

// ---------------- helpers ----------------------------------------------------
__device__ __forceinline__ uint32_t smem_u32(const void* p) {
    uint32_t a;
    asm("{ .reg .u64 t; cvta.to.shared.u64 t, %1; cvt.u32.u64 %0, t; }" : "=r"(a) : "l"(p));
    return a;
}
// pack two fp32 (x -> low half, y -> high half)
__device__ __forceinline__ uint32_t packbf(float x, float y) {
    uint32_t r;
    asm("cvt.rn.bf16x2.f32 %0, %1, %2;" : "=r"(r) : "f"(y), "f"(x));
    return r;
}
__device__ __forceinline__ void split2(float x, float y, uint32_t& hi, uint32_t& lo) {
    hi = packbf(x, y);
    float hx = __uint_as_float(hi << 16);
    float hy = __uint_as_float(hi & 0xffff0000u);
    lo = packbf(x - hx, y - hy);
}
__device__ __forceinline__ void ldsm4(uint32_t (&r)[4], uint32_t a) {
    asm volatile("ldmatrix.sync.aligned.m8n8.x4.shared.b16 {%0,%1,%2,%3}, [%4];"
        : "=r"(r[0]), "=r"(r[1]), "=r"(r[2]), "=r"(r[3]) : "r"(a));
}
__device__ __forceinline__ void ldsm4t(uint32_t (&r)[4], uint32_t a) {
    asm volatile("ldmatrix.sync.aligned.m8n8.x4.trans.shared.b16 {%0,%1,%2,%3}, [%4];"
        : "=r"(r[0]), "=r"(r[1]), "=r"(r[2]), "=r"(r[3]) : "r"(a));
}
__device__ __forceinline__ void mma16816(float4& c, const uint32_t (&a)[4],
                                         uint32_t b0, uint32_t b1) {
    asm volatile("mma.sync.aligned.m16n8k16.row.col.f32.bf16.bf16.f32 "
        "{%0,%1,%2,%3}, {%4,%5,%6,%7}, {%8,%9}, {%0,%1,%2,%3};"
        : "+f"(c.x), "+f"(c.y), "+f"(c.z), "+f"(c.w)
        : "r"(a[0]), "r"(a[1]), "r"(a[2]), "r"(a[3]), "r"(b0), "r"(b1));
}

// ---------------- kernel 0: weight transpose + bf16 split -------------------
__global__ __launch_bounds__(256) void prep_w_kernel(
    const float* __restrict__ qkv_w, const float* __restrict__ proj_w) {
    int idx = blockIdx.x * 256 + threadIdx.x;
    if (idx < 196608) {
        int n = idx >> 8, k = idx & 255;
        float v = qkv_w[k * 768 + n];
        __nv_bfloat16 h = __float2bfloat16(v);
        g_wqkv_hi[idx] = h;
        g_wqkv_lo[idx] = __float2bfloat16(v - __bfloat162float(h));
    } else {
        int j = idx - 196608;
        int n = j >> 8, k = j & 255;
        float v = proj_w[k * 256 + n];
        __nv_bfloat16 h = __float2bfloat16(v);
        g_wp_hi[j] = h;
        g_wp_lo[j] = __float2bfloat16(v - __bfloat162float(h));
    }
}

// ---------------- kernel 1: MLP -> bq, bk (bf16 hi/lo) ----------------------
__global__ __launch_bounds__(128) void bias_mlp_kernel(
    const float* __restrict__ m1w, const float* __restrict__ m1b,
    const float* __restrict__ m2w, const float* __restrict__ bs) {
    __shared__ float hf[128];
    const int n = blockIdx.x;
    const int t = threadIdx.x;
    const float invden = 1.0f / log1pf(15.0f);
    const float cy = log1pf((float)(n >> 4)) * invden;
    const float cx = log1pf((float)(n & 15)) * invden;
    {
        float z = cy * m1w[t] + cx * m1w[128 + t] + m1b[t];
        hf[t] = 0.5f * z * (1.0f + erff(z * 0.70710678118654752f));
    }
    __syncthreads();
    const float bscale = bs[0];
    for (int c = t; c < 512; c += 128) {
        float acc = 0.0f;
        #pragma unroll 8
        for (int j = 0; j < 128; j++) acc += hf[j] * m2w[j * 512 + c];
        float sig = 1.0f / (1.0f + __expf(-acc));
        int h = c >> 6, s = (c >> 5) & 1, r = c & 31;
        float v = (s == 0) ? bscale * sig : sig;
        __nv_bfloat16 vh = __float2bfloat16(v);
        __nv_bfloat16 vl = __float2bfloat16(v - __bfloat162float(vh));
        int idx = (h * NTOK + n) * 32 + r;
        if (s == 0) { g_bqh[idx] = vh; g_bql[idx] = vl; }
        else        { g_bkh[idx] = vh; g_bkl[idx] = vl; }
    }
}

// ---------------- GEMM via mma.sync, double-buffered + prefetched -----------
// smem: 2 buffers x (hi[256][40bf16] + lo[256][40bf16]) = 2 x 40960 B
#define GEMM_BUF_BYTES 40960
#define GEMM_SMEM_BYTES (2 * GEMM_BUF_BYTES)

template <bool QKV>
__global__ __launch_bounds__(256) void gemm_mma_kernel(
    const float* __restrict__ Ain, const float* __restrict__ bias,
    const float* __restrict__ ls, float* __restrict__ outp) {
    extern __shared__ char sm[];
    const uint32_t sb = smem_u32(sm);
    const int t = threadIdx.x, w = t >> 5, lane = t & 31;
    const int m0 = blockIdx.y * 128 + w * 16;
    const int c0 = QKV ? blockIdx.x * 256 : 0;
    const int r = lane >> 2, cc = (lane & 3) * 2;
    const int lrow = (lane & 7) + ((lane >> 4) << 3);
    const int lcol2 = (((lane >> 3) & 1) << 3) * 2;

    const float* A = QKV ? Ain : (const float*)g_att;
    const __nv_bfloat16* Bh = QKV ? g_wqkv_hi : g_wp_hi;
    const __nv_bfloat16* Bl = QKV ? g_wqkv_lo : g_wp_lo;

    float4 acc[32];
    #pragma unroll
    for (int i = 0; i < 32; i++) acc[i] = make_float4(0.f, 0.f, 0.f, 0.f);

    const float* ar0 = A + (size_t)(m0 + r) * 256;
    const float* ar8 = ar0 + 8 * 256;
    const size_t gbrow = (size_t)(c0 + t) * 256;

    uint4 pbh[4], pbl[4];           // B prefetch regs (one 32-k row hi+lo)
    float2 pa[8], pa2[8];           // A prefetch regs (fp32)

    // prefetch kc=0
    #pragma unroll
    for (int u = 0; u < 4; u++) {
        pbh[u] = *(const uint4*)(Bh + gbrow + u * 8);
        pbl[u] = *(const uint4*)(Bl + gbrow + u * 8);
    }
    {
        int k0 = cc;
        pa[0] = *(const float2*)(ar0 + k0);      pa[1] = *(const float2*)(ar8 + k0);
        pa[2] = *(const float2*)(ar0 + k0 + 8);  pa[3] = *(const float2*)(ar8 + k0 + 8);
        pa[4] = *(const float2*)(ar0 + k0 + 16); pa[5] = *(const float2*)(ar8 + k0 + 16);
        pa[6] = *(const float2*)(ar0 + k0 + 24); pa[7] = *(const float2*)(ar8 + k0 + 24);
    }
    // stage buffer 0
    #pragma unroll
    for (int u = 0; u < 4; u++) {
        *(uint4*)(sm + t * 80 + u * 16) = pbh[u];
        *(uint4*)(sm + 20480 + t * 80 + u * 16) = pbl[u];
    }
    __syncthreads();

    #pragma unroll
    for (int kc = 0; kc < 8; kc++) {
        // issue prefetch for kc+1 (overlaps with compute below)
        if (kc < 7) {
            size_t gb = gbrow + (kc + 1) * 32;
            #pragma unroll
            for (int u = 0; u < 4; u++) {
                pbh[u] = *(const uint4*)(Bh + gb + u * 8);
                pbl[u] = *(const uint4*)(Bl + gb + u * 8);
            }
            int k0 = (kc + 1) * 32 + cc;
            pa2[0] = *(const float2*)(ar0 + k0);      pa2[1] = *(const float2*)(ar8 + k0);
            pa2[2] = *(const float2*)(ar0 + k0 + 8);  pa2[3] = *(const float2*)(ar8 + k0 + 8);
            pa2[4] = *(const float2*)(ar0 + k0 + 16); pa2[5] = *(const float2*)(ar8 + k0 + 16);
            pa2[6] = *(const float2*)(ar0 + k0 + 24); pa2[7] = *(const float2*)(ar8 + k0 + 24);
        }
        // split current A chunk
        uint32_t ah[2][4], al[2][4];
        #pragma unroll
        for (int kk = 0; kk < 2; kk++) {
            split2(pa[kk*4+0].x, pa[kk*4+0].y, ah[kk][0], al[kk][0]);
            split2(pa[kk*4+1].x, pa[kk*4+1].y, ah[kk][1], al[kk][1]);
            split2(pa[kk*4+2].x, pa[kk*4+2].y, ah[kk][2], al[kk][2]);
            split2(pa[kk*4+3].x, pa[kk*4+3].y, ah[kk][3], al[kk][3]);
        }
        // compute on current buffer
        const uint32_t bufb = sb + (kc & 1) * GEMM_BUF_BYTES;
        #pragma unroll
        for (int n16 = 0; n16 < 16; n16++) {
            uint32_t off = (uint32_t)((n16 * 16 + lrow) * 80) + lcol2;
            uint32_t rh0[4], rh1[4], rl0[4], rl1[4];
            ldsm4(rh0, bufb + off);
            ldsm4(rh1, bufb + off + 32);
            ldsm4(rl0, bufb + 20480 + off);
            ldsm4(rl1, bufb + 20480 + off + 32);
            float4& cA = acc[2 * n16];
            float4& cB = acc[2 * n16 + 1];
            mma16816(cA, ah[0], rh0[0], rh0[1]); mma16816(cA, ah[1], rh1[0], rh1[1]);
            mma16816(cA, al[0], rh0[0], rh0[1]); mma16816(cA, al[1], rh1[0], rh1[1]);
            mma16816(cA, ah[0], rl0[0], rl0[1]); mma16816(cA, ah[1], rl1[0], rl1[1]);
            mma16816(cB, ah[0], rh0[2], rh0[3]); mma16816(cB, ah[1], rh1[2], rh1[3]);
            mma16816(cB, al[0], rh0[2], rh0[3]); mma16816(cB, al[1], rh1[2], rh1[3]);
            mma16816(cB, ah[0], rl0[2], rl0[3]); mma16816(cB, ah[1], rl1[2], rl1[3]);
        }
        // stage next buffer + rotate A regs
        if (kc < 7) {
            char* dst = sm + ((kc + 1) & 1) * GEMM_BUF_BYTES;
            #pragma unroll
            for (int u = 0; u < 4; u++) {
                *(uint4*)(dst + t * 80 + u * 16) = pbh[u];
                *(uint4*)(dst + 20480 + t * 80 + u * 16) = pbl[u];
            }
            __syncthreads();
            #pragma unroll
            for (int u = 0; u < 8; u++) pa[u] = pa2[u];
        }
    }

    const int mrow0 = m0 + r;
    if (QKV) {
        const int s = blockIdx.x;
        __nv_bfloat16* dh = (s == 0) ? g_qh : (s == 1 ? g_kh : g_vh);
        __nv_bfloat16* dl = (s == 0) ? g_ql : (s == 1 ? g_kl : g_vl);
        const int bidx = mrow0 >> 8, n0r = mrow0 & 255, n1r = n0r + 8;
        #pragma unroll
        for (int ti = 0; ti < 32; ti++) {
            int c = ti * 8 + cc;
            float2 bb = *(const float2*)(bias + c0 + c);
            float scv = (s == 0) ? __ldg(ls + (c >> 5)) : 1.0f;
            float v00 = (acc[ti].x + bb.x) * scv, v01 = (acc[ti].y + bb.y) * scv;
            float v10 = (acc[ti].z + bb.x) * scv, v11 = (acc[ti].w + bb.y) * scv;
            int h = c >> 5, d = c & 31;
            size_t i0 = ((size_t)(bidx * 8 + h) * 256 + n0r) * 32 + d;
            size_t i1 = ((size_t)(bidx * 8 + h) * 256 + n1r) * 32 + d;
            uint32_t hi, lo;
            split2(v00, v01, hi, lo);
            *(uint32_t*)&dh[i0] = hi; *(uint32_t*)&dl[i0] = lo;
            split2(v10, v11, hi, lo);
            *(uint32_t*)&dh[i1] = hi; *(uint32_t*)&dl[i1] = lo;
        }
    } else {
        #pragma unroll
        for (int ti = 0; ti < 32; ti++) {
            int c = ti * 8 + cc;
            float2 bb = *(const float2*)(bias + c);
            *(float2*)(outp + (size_t)mrow0 * 256 + c) =
                make_float2(acc[ti].x + bb.x, acc[ti].y + bb.y);
            *(float2*)(outp + (size_t)(mrow0 + 8) * 256 + c) =
                make_float2(acc[ti].z + bb.x, acc[ti].w + bb.y);
        }
    }
}

// ---------------- attention kernel (per b,h), HMMA (validated) --------------
#define AS_KHI   0
#define AS_KLO   20480
#define AS_BKH   40960
#define AS_BKL   61440
#define AS_VHI   81920
#define AS_VLO   102400
#define AS_VMEAN 122880
#define AS_RED   123008
#define ATTN_SMEM_BYTES (123008 + 1024)

__global__ __launch_bounds__(256) void attn_mma_kernel(const float* __restrict__ vrs) {
    extern __shared__ char sm[];
    const uint32_t sb = smem_u32(sm);
    const int bh = blockIdx.x;
    const int b = bh >> 3, h = bh & 7;
    const int t = threadIdx.x, w = t >> 5, lane = t & 31;
    const int r = lane >> 2, cc = (lane & 3) * 2;
    const int lrow = (lane & 7) + ((lane >> 4) << 3);
    const int lcol2 = (((lane >> 3) & 1) << 3) * 2;
    const int lrowT = lane & 15;
    const int lcolT2 = ((lane >> 4) << 3) * 2;

    {
        size_t gk = (size_t)bh * 8192 + (size_t)t * 32;
        size_t gb = (size_t)h * 8192 + (size_t)t * 32;
        #pragma unroll
        for (int u = 0; u < 4; u++) {
            *(uint4*)(sm + AS_KHI + t * 80 + u * 16) = *(const uint4*)(g_kh + gk + u * 8);
            *(uint4*)(sm + AS_KLO + t * 80 + u * 16) = *(const uint4*)(g_kl + gk + u * 8);
            *(uint4*)(sm + AS_VHI + t * 80 + u * 16) = *(const uint4*)(g_vh + gk + u * 8);
            *(uint4*)(sm + AS_VLO + t * 80 + u * 16) = *(const uint4*)(g_vl + gk + u * 8);
            *(uint4*)(sm + AS_BKH + t * 80 + u * 16) = *(const uint4*)(g_bkh + gb + u * 8);
            *(uint4*)(sm + AS_BKL + t * 80 + u * 16) = *(const uint4*)(g_bkl + gb + u * 8);
        }
    }
    __syncthreads();

    {
        int d = t & 31, grp = t >> 5;
        float s = 0.0f;
        for (int n = grp * 32; n < grp * 32 + 32; n++) {
            uint16_t hv = *(const uint16_t*)(sm + AS_VHI + n * 80 + d * 2);
            uint16_t lv = *(const uint16_t*)(sm + AS_VLO + n * 80 + d * 2);
            s += __uint_as_float(((uint32_t)hv) << 16) + __uint_as_float(((uint32_t)lv) << 16);
        }
        ((float*)(sm + AS_RED))[grp * 32 + d] = s;
    }
    __syncthreads();
    if (t < 32) {
        float s = 0.0f;
        #pragma unroll
        for (int g = 0; g < 8; g++) s += ((float*)(sm + AS_RED))[g * 32 + t];
        ((float*)(sm + AS_VMEAN))[t] = s * (1.0f / 256.0f) * __ldg(vrs + h);
    }
    __syncthreads();

    for (int pass = 0; pass < 2; pass++) {
        const int tok0 = pass * 128 + w * 16 + r;
        uint32_t aqh[2][4], aql[2][4], abh[2][4], abl[2][4];
        {
            size_t q0 = (size_t)bh * 8192 + (size_t)tok0 * 32;
            size_t b0 = (size_t)h * 8192 + (size_t)tok0 * 32;
            #pragma unroll
            for (int kk = 0; kk < 2; kk++) {
                int o = kk * 16 + cc;
                aqh[kk][0] = *(const uint32_t*)(g_qh + q0 + o);
                aqh[kk][1] = *(const uint32_t*)(g_qh + q0 + 256 + o);
                aqh[kk][2] = *(const uint32_t*)(g_qh + q0 + o + 8);
                aqh[kk][3] = *(const uint32_t*)(g_qh + q0 + 256 + o + 8);
                aql[kk][0] = *(const uint32_t*)(g_ql + q0 + o);
                aql[kk][1] = *(const uint32_t*)(g_ql + q0 + 256 + o);
                aql[kk][2] = *(const uint32_t*)(g_ql + q0 + o + 8);
                aql[kk][3] = *(const uint32_t*)(g_ql + q0 + 256 + o + 8);
                abh[kk][0] = *(const uint32_t*)(g_bqh + b0 + o);
                abh[kk][1] = *(const uint32_t*)(g_bqh + b0 + 256 + o);
                abh[kk][2] = *(const uint32_t*)(g_bqh + b0 + o + 8);
                abh[kk][3] = *(const uint32_t*)(g_bqh + b0 + 256 + o + 8);
                abl[kk][0] = *(const uint32_t*)(g_bql + b0 + o);
                abl[kk][1] = *(const uint32_t*)(g_bql + b0 + 256 + o);
                abl[kk][2] = *(const uint32_t*)(g_bql + b0 + o + 8);
                abl[kk][3] = *(const uint32_t*)(g_bql + b0 + 256 + o + 8);
            }
        }

        float4 sc[32];
        #pragma unroll
        for (int i = 0; i < 32; i++) sc[i] = make_float4(0.f, 0.f, 0.f, 0.f);
        #pragma unroll
        for (int n16 = 0; n16 < 16; n16++) {
            uint32_t off = (uint32_t)((n16 * 16 + lrow) * 80) + lcol2;
            uint32_t kh0[4], kh1[4], kl0[4], kl1[4];
            uint32_t bh0[4], bh1[4], bl0[4], bl1[4];
            ldsm4(kh0, sb + AS_KHI + off); ldsm4(kh1, sb + AS_KHI + off + 32);
            ldsm4(kl0, sb + AS_KLO + off); ldsm4(kl1, sb + AS_KLO + off + 32);
            ldsm4(bh0, sb + AS_BKH + off); ldsm4(bh1, sb + AS_BKH + off + 32);
            ldsm4(bl0, sb + AS_BKL + off); ldsm4(bl1, sb + AS_BKL + off + 32);
            float4& cA = sc[2 * n16];
            float4& cB = sc[2 * n16 + 1];
            mma16816(cA, aqh[0], kh0[0], kh0[1]); mma16816(cA, aqh[1], kh1[0], kh1[1]);
            mma16816(cA, aql[0], kh0[0], kh0[1]); mma16816(cA, aql[1], kh1[0], kh1[1]);
            mma16816(cA, aqh[0], kl0[0], kl0[1]); mma16816(cA, aqh[1], kl1[0], kl1[1]);
            mma16816(cA, abh[0], bh0[0], bh0[1]); mma16816(cA, abh[1], bh1[0], bh1[1]);
            mma16816(cA, abl[0], bh0[0], bh0[1]); mma16816(cA, abl[1], bh1[0], bh1[1]);
            mma16816(cA, abh[0], bl0[0], bl0[1]); mma16816(cA, abh[1], bl1[0], bl1[1]);
            mma16816(cB, aqh[0], kh0[2], kh0[3]); mma16816(cB, aqh[1], kh1[2], kh1[3]);
            mma16816(cB, aql[0], kh0[2], kh0[3]); mma16816(cB, aql[1], kh1[2], kh1[3]);
            mma16816(cB, aqh[0], kl0[2], kl0[3]); mma16816(cB, aqh[1], kl1[2], kl1[3]);
            mma16816(cB, abh[0], bh0[2], bh0[3]); mma16816(cB, abh[1], bh1[2], bh1[3]);
            mma16816(cB, abl[0], bh0[2], bh0[3]); mma16816(cB, abl[1], bh1[2], bh1[3]);
            mma16816(cB, abh[0], bl0[2], bl0[3]); mma16816(cB, abh[1], bl1[2], bl1[3]);
        }

        float m0 = -1e30f, m1 = -1e30f;
        #pragma unroll
        for (int i = 0; i < 32; i++) {
            m0 = fmaxf(m0, fmaxf(sc[i].x, sc[i].y));
            m1 = fmaxf(m1, fmaxf(sc[i].z, sc[i].w));
        }
        m0 = fmaxf(m0, __shfl_xor_sync(0xffffffffu, m0, 1));
        m0 = fmaxf(m0, __shfl_xor_sync(0xffffffffu, m0, 2));
        m1 = fmaxf(m1, __shfl_xor_sync(0xffffffffu, m1, 1));
        m1 = fmaxf(m1, __shfl_xor_sync(0xffffffffu, m1, 2));
        float s0 = 0.f, s1 = 0.f;
        #pragma unroll
        for (int i = 0; i < 32; i++) {
            sc[i].x = __expf(sc[i].x - m0); sc[i].y = __expf(sc[i].y - m0);
            sc[i].z = __expf(sc[i].z - m1); sc[i].w = __expf(sc[i].w - m1);
            s0 += sc[i].x + sc[i].y; s1 += sc[i].z + sc[i].w;
        }
        s0 += __shfl_xor_sync(0xffffffffu, s0, 1);
        s0 += __shfl_xor_sync(0xffffffffu, s0, 2);
        s1 += __shfl_xor_sync(0xffffffffu, s1, 1);
        s1 += __shfl_xor_sync(0xffffffffu, s1, 2);
        float inv0 = 1.0f / s0, inv1 = 1.0f / s1;

        float4 o[4];
        #pragma unroll
        for (int i = 0; i < 4; i++) o[i] = make_float4(0.f, 0.f, 0.f, 0.f);
        #pragma unroll
        for (int tk = 0; tk < 16; tk++) {
            uint32_t Ahi[4], Alo[4];
            split2(sc[2 * tk].x,     sc[2 * tk].y,     Ahi[0], Alo[0]);
            split2(sc[2 * tk].z,     sc[2 * tk].w,     Ahi[1], Alo[1]);
            split2(sc[2 * tk + 1].x, sc[2 * tk + 1].y, Ahi[2], Alo[2]);
            split2(sc[2 * tk + 1].z, sc[2 * tk + 1].w, Ahi[3], Alo[3]);
            uint32_t off = (uint32_t)((tk * 16 + lrowT) * 80) + lcolT2;
            uint32_t vh0[4], vh1[4], vl0[4], vl1[4];
            ldsm4t(vh0, sb + AS_VHI + off); ldsm4t(vh1, sb + AS_VHI + off + 32);
            ldsm4t(vl0, sb + AS_VLO + off); ldsm4t(vl1, sb + AS_VLO + off + 32);
            mma16816(o[0], Ahi, vh0[0], vh0[1]); mma16816(o[1], Ahi, vh0[2], vh0[3]);
            mma16816(o[2], Ahi, vh1[0], vh1[1]); mma16816(o[3], Ahi, vh1[2], vh1[3]);
            mma16816(o[0], Alo, vh0[0], vh0[1]); mma16816(o[1], Alo, vh0[2], vh0[3]);
            mma16816(o[2], Alo, vh1[0], vh1[1]); mma16816(o[3], Alo, vh1[2], vh1[3]);
            mma16816(o[0], Ahi, vl0[0], vl0[1]); mma16816(o[1], Ahi, vl0[2], vl0[3]);
            mma16816(o[2], Ahi, vl1[0], vl1[1]); mma16816(o[3], Ahi, vl1[2], vl1[3]);
        }

        const float* vmean = (const float*)(sm + AS_VMEAN);
        float* out0 = g_att + ((size_t)b * 256 + tok0) * 256 + h * 32;
        float* out1 = out0 + 8 * 256;
        #pragma unroll
        for (int dt = 0; dt < 4; dt++) {
            int d = dt * 8 + cc;
            float vm0 = vmean[d], vm1 = vmean[d + 1];
            *(float2*)(out0 + d) = make_float2(o[dt].x * inv0 + vm0, o[dt].y * inv0 + vm1);
            *(float2*)(out1 + d) = make_float2(o[dt].z * inv1 + vm0, o[dt].w * inv1 + vm1);
        }
    }
}

// ---------------- launch -----------------------------------------------------
extern "C" void kernel_launch(void* const* d_in, const int* in_sizes, int n_in,
                              void* d_out, int out_size) {
    const float* x             = (const float*)d_in[0];
    const float* qkv_w         = (const float*)d_in[1];
    const float* qkv_b         = (const float*)d_in[2];
    const float* proj_w        = (const float*)d_in[3];
    const float* proj_b        = (const float*)d_in[4];
    const float* logit_scale   = (const float*)d_in[5];
    const float* val_res_scale = (const float*)d_in[6];
    const float* mlp1_w        = (const float*)d_in[7];
    const float* mlp1_b        = (const float*)d_in[8];
    const float* mlp2_w        = (const float*)d_in[9];
    const float* bias_scale    = (const float*)d_in[10];
    float* out = (float*)d_out;

    cudaFuncSetAttribute(attn_mma_kernel, cudaFuncAttributeMaxDynamicSharedMemorySize,
                         ATTN_SMEM_BYTES);
    cudaFuncSetAttribute(gemm_mma_kernel<true>, cudaFuncAttributeMaxDynamicSharedMemorySize,
                         GEMM_SMEM_BYTES);
    cudaFuncSetAttribute(gemm_mma_kernel<false>, cudaFuncAttributeMaxDynamicSharedMemorySize,
                         GEMM_SMEM_BYTES);

    prep_w_kernel<<<1024, 256>>>(qkv_w, proj_w);
    bias_mlp_kernel<<<256, 128>>>(mlp1_w, mlp1_b, mlp2_w, bias_scale);
    gemm_mma_kernel<true><<<dim3(3, 1024), 256, GEMM_SMEM_BYTES>>>(
        x, qkv_b, logit_scale, nullptr);
    attn_mma_kernel<<<4096, 256, ATTN_SMEM_BYTES>>>(val_res_scale);
    gemm_mma_kernel<false><<<dim3(1, 1024), 256, GEMM_SMEM_BYTES>>>(
        x /*unused*/, proj_b, nullptr, out);
}

// round 8
// speedup vs baseline: 2.5873x; 1.0041x over previous
#include <cuda_runtime.h>
#include <cuda_bf16.h>
#include <math.h>
#include <stdint.h>

#define BDIM 512
#define NTOK 256
#define HNUM 8
#define HD   32

// ---------------- scratch (device globals; referenced ONLY in device code) --
__device__ __align__(256) __nv_bfloat16 g_qh[BDIM*HNUM*NTOK*HD];
__device__ __align__(256) __nv_bfloat16 g_ql[BDIM*HNUM*NTOK*HD];
__device__ __align__(256) __nv_bfloat16 g_kh[BDIM*HNUM*NTOK*HD];
__device__ __align__(256) __nv_bfloat16 g_kl[BDIM*HNUM*NTOK*HD];
__device__ __align__(256) __nv_bfloat16 g_vh[BDIM*HNUM*NTOK*HD];
__device__ __align__(256) __nv_bfloat16 g_vl[BDIM*HNUM*NTOK*HD];
__device__ __align__(256) float g_att[BDIM*NTOK*256];                // 134 MB
__device__ __align__(256) __nv_bfloat16 g_wqkv_hi[768*256];
__device__ __align__(256) __nv_bfloat16 g_wqkv_lo[768*256];
__device__ __align__(256) __nv_bfloat16 g_wp_hi[256*256];
__device__ __align__(256) __nv_bfloat16 g_wp_lo[256*256];
__device__ __align__(256) __nv_bfloat16 g_bqh[HNUM*NTOK*HD];
__device__ __align__(256) __nv_bfloat16 g_bql[HNUM*NTOK*HD];
__device__ __align__(256) __nv_bfloat16 g_bkh[HNUM*NTOK*HD];
__device__ __align__(256) __nv_bfloat16 g_bkl[HNUM*NTOK*HD];

// ---------------- helpers ----------------------------------------------------
__device__ __forceinline__ uint32_t smem_u32(const void* p) {
    uint32_t a;
    asm("{ .reg .u64 t; cvta.to.shared.u64 t, %1; cvt.u32.u64 %0, t; }" : "=r"(a) : "l"(p));
    return a;
}
__device__ __forceinline__ uint32_t packbf(float x, float y) {
    uint32_t r;
    asm("cvt.rn.bf16x2.f32 %0, %1, %2;" : "=r"(r) : "f"(y), "f"(x));
    return r;
}
__device__ __forceinline__ void split2(float x, float y, uint32_t& hi, uint32_t& lo) {
    hi = packbf(x, y);
    float hx = __uint_as_float(hi << 16);
    float hy = __uint_as_float(hi & 0xffff0000u);
    lo = packbf(x - hx, y - hy);
}
__device__ __forceinline__ void ldsm4(uint32_t (&r)[4], uint32_t a) {
    asm volatile("ldmatrix.sync.aligned.m8n8.x4.shared.b16 {%0,%1,%2,%3}, [%4];"
        : "=r"(r[0]), "=r"(r[1]), "=r"(r[2]), "=r"(r[3]) : "r"(a));
}
__device__ __forceinline__ void ldsm4t(uint32_t (&r)[4], uint32_t a) {
    asm volatile("ldmatrix.sync.aligned.m8n8.x4.trans.shared.b16 {%0,%1,%2,%3}, [%4];"
        : "=r"(r[0]), "=r"(r[1]), "=r"(r[2]), "=r"(r[3]) : "r"(a));
}
__device__ __forceinline__ void mma16816(float4& c, const uint32_t (&a)[4],
                                         uint32_t b0, uint32_t b1) {
    asm volatile("mma.sync.aligned.m16n8k16.row.col.f32.bf16.bf16.f32 "
        "{%0,%1,%2,%3}, {%4,%5,%6,%7}, {%8,%9}, {%0,%1,%2,%3};"
        : "+f"(c.x), "+f"(c.y), "+f"(c.z), "+f"(c.w)
        : "r"(a[0]), "r"(a[1]), "r"(a[2]), "r"(a[3]), "r"(b0), "r"(b1));
}
__device__ __forceinline__ void cpasync16(uint32_t dst, const void* src) {
    asm volatile("cp.async.cg.shared.global [%0], [%1], 16;" :: "r"(dst), "l"(src));
}
#define CP_COMMIT() asm volatile("cp.async.commit_group;" ::: "memory")
#define CP_WAIT(n)  asm volatile("cp.async.wait_group %0;" :: "n"(n) : "memory")

// ---------------- kernel 0: weight transpose + bf16 split -------------------
__global__ __launch_bounds__(256) void prep_w_kernel(
    const float* __restrict__ qkv_w, const float* __restrict__ proj_w) {
    int idx = blockIdx.x * 256 + threadIdx.x;
    if (idx < 196608) {
        int n = idx >> 8, k = idx & 255;
        float v = qkv_w[k * 768 + n];
        __nv_bfloat16 h = __float2bfloat16(v);
        g_wqkv_hi[idx] = h;
        g_wqkv_lo[idx] = __float2bfloat16(v - __bfloat162float(h));
    } else {
        int j = idx - 196608;
        int n = j >> 8, k = j & 255;
        float v = proj_w[k * 256 + n];
        __nv_bfloat16 h = __float2bfloat16(v);
        g_wp_hi[j] = h;
        g_wp_lo[j] = __float2bfloat16(v - __bfloat162float(h));
    }
}

// ---------------- kernel 1: MLP -> bq, bk (bf16 hi/lo) ----------------------
__global__ __launch_bounds__(128) void bias_mlp_kernel(
    const float* __restrict__ m1w, const float* __restrict__ m1b,
    const float* __restrict__ m2w, const float* __restrict__ bs) {
    __shared__ float hf[128];
    const int n = blockIdx.x;
    const int t = threadIdx.x;
    const float invden = 1.0f / log1pf(15.0f);
    const float cy = log1pf((float)(n >> 4)) * invden;
    const float cx = log1pf((float)(n & 15)) * invden;
    {
        float z = cy * m1w[t] + cx * m1w[128 + t] + m1b[t];
        hf[t] = 0.5f * z * (1.0f + erff(z * 0.70710678118654752f));
    }
    __syncthreads();
    const float bscale = bs[0];
    for (int c = t; c < 512; c += 128) {
        float acc = 0.0f;
        #pragma unroll 8
        for (int j = 0; j < 128; j++) acc += hf[j] * m2w[j * 512 + c];
        float sig = 1.0f / (1.0f + __expf(-acc));
        int h = c >> 6, s = (c >> 5) & 1, r = c & 31;
        float v = (s == 0) ? bscale * sig : sig;
        __nv_bfloat16 vh = __float2bfloat16(v);
        __nv_bfloat16 vl = __float2bfloat16(v - __bfloat162float(vh));
        int idx = (h * NTOK + n) * 32 + r;
        if (s == 0) { g_bqh[idx] = vh; g_bql[idx] = vl; }
        else        { g_bkh[idx] = vh; g_bkl[idx] = vl; }
    }
}

// ---------------- GEMM via mma.sync, n128 tile, cp.async double-buffer ------
// smem per buffer: hi[128][40bf16]=10240 + lo=10240 -> 20480; x2 = 40960
#define GEMM_BUF_BYTES 20480
#define GEMM_SMEM_BYTES (2 * GEMM_BUF_BYTES)

template <bool QKV>
__global__ __launch_bounds__(256, 2) void gemm_mma_kernel(
    const float* __restrict__ Ain, const float* __restrict__ bias,
    const float* __restrict__ ls, float* __restrict__ outp) {
    extern __shared__ char sm[];
    const uint32_t sb = smem_u32(sm);
    const int t = threadIdx.x, w = t >> 5, lane = t & 31;
    const int m0 = blockIdx.y * 128 + w * 16;
    const int c0 = blockIdx.x * 128;
    const int r = lane >> 2, cc = (lane & 3) * 2;
    const int lrow = (lane & 7) + ((lane >> 4) << 3);
    const int lcol2 = (((lane >> 3) & 1) << 3) * 2;

    const float* A = QKV ? Ain : (const float*)g_att;
    const __nv_bfloat16* Bh = QKV ? g_wqkv_hi : g_wp_hi;
    const __nv_bfloat16* Bl = QKV ? g_wqkv_lo : g_wp_lo;

    float4 acc[16];
    #pragma unroll
    for (int i = 0; i < 16; i++) acc[i] = make_float4(0.f, 0.f, 0.f, 0.f);

    const float* ar0 = A + (size_t)(m0 + r) * 256;
    const float* ar8 = ar0 + 8 * 256;

    // cp.async staging: t<128 -> hi row t ; t>=128 -> lo row t-128
    const int srow = t & 127;
    const bool is_lo = t >= 128;
    const __nv_bfloat16* bsrc = (is_lo ? Bl : Bh) + (size_t)(c0 + srow) * 256;
    const uint32_t sdst_base = sb + (is_lo ? 10240 : 0) + srow * 80;

    // prologue: stage chunk 0 -> buf0
    #pragma unroll
    for (int u = 0; u < 4; u++) cpasync16(sdst_base + u * 16, bsrc + u * 8);
    CP_COMMIT();

    #pragma unroll
    for (int kc = 0; kc < 8; kc++) {
        if (kc < 7) {
            uint32_t dst = sdst_base + ((kc + 1) & 1) * GEMM_BUF_BYTES;
            const __nv_bfloat16* src = bsrc + (kc + 1) * 32;
            #pragma unroll
            for (int u = 0; u < 4; u++) cpasync16(dst + u * 16, src + u * 8);
            CP_COMMIT();
        }
        // A chunk kc: load + split (overlaps with cp.async)
        uint32_t ah[2][4], al[2][4];
        {
            int k0 = kc * 32 + cc;
            float2 v;
            #pragma unroll
            for (int kk = 0; kk < 2; kk++) {
                int o = k0 + kk * 16;
                v = *(const float2*)(ar0 + o);      split2(v.x, v.y, ah[kk][0], al[kk][0]);
                v = *(const float2*)(ar8 + o);      split2(v.x, v.y, ah[kk][1], al[kk][1]);
                v = *(const float2*)(ar0 + o + 8);  split2(v.x, v.y, ah[kk][2], al[kk][2]);
                v = *(const float2*)(ar8 + o + 8);  split2(v.x, v.y, ah[kk][3], al[kk][3]);
            }
        }
        if (kc < 7) CP_WAIT(1); else CP_WAIT(0);
        __syncthreads();

        const uint32_t bufb = sb + (kc & 1) * GEMM_BUF_BYTES;
        #pragma unroll
        for (int n16 = 0; n16 < 8; n16++) {
            uint32_t off = (uint32_t)((n16 * 16 + lrow) * 80) + lcol2;
            uint32_t rh0[4], rh1[4], rl0[4], rl1[4];
            ldsm4(rh0, bufb + off);
            ldsm4(rh1, bufb + off + 32);
            ldsm4(rl0, bufb + 10240 + off);
            ldsm4(rl1, bufb + 10240 + off + 32);
            float4& cA = acc[2 * n16];
            float4& cB = acc[2 * n16 + 1];
            mma16816(cA, ah[0], rh0[0], rh0[1]); mma16816(cA, ah[1], rh1[0], rh1[1]);
            mma16816(cA, al[0], rh0[0], rh0[1]); mma16816(cA, al[1], rh1[0], rh1[1]);
            mma16816(cA, ah[0], rl0[0], rl0[1]); mma16816(cA, ah[1], rl1[0], rl1[1]);
            mma16816(cB, ah[0], rh0[2], rh0[3]); mma16816(cB, ah[1], rh1[2], rh1[3]);
            mma16816(cB, al[0], rh0[2], rh0[3]); mma16816(cB, al[1], rh1[2], rh1[3]);
            mma16816(cB, ah[0], rl0[2], rl0[3]); mma16816(cB, ah[1], rl1[2], rl1[3]);
        }
        __syncthreads();
    }

    const int mrow0 = m0 + r;
    if (QKV) {
        const int s = blockIdx.x >> 1;
        __nv_bfloat16* dh = (s == 0) ? g_qh : (s == 1 ? g_kh : g_vh);
        __nv_bfloat16* dl = (s == 0) ? g_ql : (s == 1 ? g_kl : g_vl);
        const int bidx = mrow0 >> 8, n0r = mrow0 & 255, n1r = n0r + 8;
        #pragma unroll
        for (int ti = 0; ti < 16; ti++) {
            int c = c0 + ti * 8 + cc;
            float2 bb = *(const float2*)(bias + c);
            int rem = c & 255;
            int h = rem >> 5, d = rem & 31;
            float scv = (s == 0) ? __ldg(ls + h) : 1.0f;
            float v00 = (acc[ti].x + bb.x) * scv, v01 = (acc[ti].y + bb.y) * scv;
            float v10 = (acc[ti].z + bb.x) * scv, v11 = (acc[ti].w + bb.y) * scv;
            size_t i0 = ((size_t)(bidx * 8 + h) * 256 + n0r) * 32 + d;
            size_t i1 = ((size_t)(bidx * 8 + h) * 256 + n1r) * 32 + d;
            uint32_t hi, lo;
            split2(v00, v01, hi, lo);
            *(uint32_t*)&dh[i0] = hi; *(uint32_t*)&dl[i0] = lo;
            split2(v10, v11, hi, lo);
            *(uint32_t*)&dh[i1] = hi; *(uint32_t*)&dl[i1] = lo;
        }
    } else {
        #pragma unroll
        for (int ti = 0; ti < 16; ti++) {
            int c = c0 + ti * 8 + cc;
            float2 bb = *(const float2*)(bias + c);
            *(float2*)(outp + (size_t)mrow0 * 256 + c) =
                make_float2(acc[ti].x + bb.x, acc[ti].y + bb.y);
            *(float2*)(outp + (size_t)(mrow0 + 8) * 256 + c) =
                make_float2(acc[ti].z + bb.x, acc[ti].w + bb.y);
        }
    }
}

// ---------------- attention kernel (per b,h), HMMA (validated, untouched) ---
#define AS_KHI   0
#define AS_KLO   20480
#define AS_BKH   40960
#define AS_BKL   61440
#define AS_VHI   81920
#define AS_VLO   102400
#define AS_VMEAN 122880
#define AS_RED   123008
#define ATTN_SMEM_BYTES (123008 + 1024)

__global__ __launch_bounds__(256) void attn_mma_kernel(const float* __restrict__ vrs) {
    extern __shared__ char sm[];
    const uint32_t sb = smem_u32(sm);
    const int bh = blockIdx.x;
    const int b = bh >> 3, h = bh & 7;
    const int t = threadIdx.x, w = t >> 5, lane = t & 31;
    const int r = lane >> 2, cc = (lane & 3) * 2;
    const int lrow = (lane & 7) + ((lane >> 4) << 3);
    const int lcol2 = (((lane >> 3) & 1) << 3) * 2;
    const int lrowT = lane & 15;
    const int lcolT2 = ((lane >> 4) << 3) * 2;

    {
        size_t gk = (size_t)bh * 8192 + (size_t)t * 32;
        size_t gb = (size_t)h * 8192 + (size_t)t * 32;
        #pragma unroll
        for (int u = 0; u < 4; u++) {
            *(uint4*)(sm + AS_KHI + t * 80 + u * 16) = *(const uint4*)(g_kh + gk + u * 8);
            *(uint4*)(sm + AS_KLO + t * 80 + u * 16) = *(const uint4*)(g_kl + gk + u * 8);
            *(uint4*)(sm + AS_VHI + t * 80 + u * 16) = *(const uint4*)(g_vh + gk + u * 8);
            *(uint4*)(sm + AS_VLO + t * 80 + u * 16) = *(const uint4*)(g_vl + gk + u * 8);
            *(uint4*)(sm + AS_BKH + t * 80 + u * 16) = *(const uint4*)(g_bkh + gb + u * 8);
            *(uint4*)(sm + AS_BKL + t * 80 + u * 16) = *(const uint4*)(g_bkl + gb + u * 8);
        }
    }
    __syncthreads();

    {
        int d = t & 31, grp = t >> 5;
        float s = 0.0f;
        for (int n = grp * 32; n < grp * 32 + 32; n++) {
            uint16_t hv = *(const uint16_t*)(sm + AS_VHI + n * 80 + d * 2);
            uint16_t lv = *(const uint16_t*)(sm + AS_VLO + n * 80 + d * 2);
            s += __uint_as_float(((uint32_t)hv) << 16) + __uint_as_float(((uint32_t)lv) << 16);
        }
        ((float*)(sm + AS_RED))[grp * 32 + d] = s;
    }
    __syncthreads();
    if (t < 32) {
        float s = 0.0f;
        #pragma unroll
        for (int g = 0; g < 8; g++) s += ((float*)(sm + AS_RED))[g * 32 + t];
        ((float*)(sm + AS_VMEAN))[t] = s * (1.0f / 256.0f) * __ldg(vrs + h);
    }
    __syncthreads();

    for (int pass = 0; pass < 2; pass++) {
        const int tok0 = pass * 128 + w * 16 + r;
        uint32_t aqh[2][4], aql[2][4], abh[2][4], abl[2][4];
        {
            size_t q0 = (size_t)bh * 8192 + (size_t)tok0 * 32;
            size_t b0 = (size_t)h * 8192 + (size_t)tok0 * 32;
            #pragma unroll
            for (int kk = 0; kk < 2; kk++) {
                int o = kk * 16 + cc;
                aqh[kk][0] = *(const uint32_t*)(g_qh + q0 + o);
                aqh[kk][1] = *(const uint32_t*)(g_qh + q0 + 256 + o);
                aqh[kk][2] = *(const uint32_t*)(g_qh + q0 + o + 8);
                aqh[kk][3] = *(const uint32_t*)(g_qh + q0 + 256 + o + 8);
                aql[kk][0] = *(const uint32_t*)(g_ql + q0 + o);
                aql[kk][1] = *(const uint32_t*)(g_ql + q0 + 256 + o);
                aql[kk][2] = *(const uint32_t*)(g_ql + q0 + o + 8);
                aql[kk][3] = *(const uint32_t*)(g_ql + q0 + 256 + o + 8);
                abh[kk][0] = *(const uint32_t*)(g_bqh + b0 + o);
                abh[kk][1] = *(const uint32_t*)(g_bqh + b0 + 256 + o);
                abh[kk][2] = *(const uint32_t*)(g_bqh + b0 + o + 8);
                abh[kk][3] = *(const uint32_t*)(g_bqh + b0 + 256 + o + 8);
                abl[kk][0] = *(const uint32_t*)(g_bql + b0 + o);
                abl[kk][1] = *(const uint32_t*)(g_bql + b0 + 256 + o);
                abl[kk][2] = *(const uint32_t*)(g_bql + b0 + o + 8);
                abl[kk][3] = *(const uint32_t*)(g_bql + b0 + 256 + o + 8);
            }
        }

        float4 sc[32];
        #pragma unroll
        for (int i = 0; i < 32; i++) sc[i] = make_float4(0.f, 0.f, 0.f, 0.f);
        #pragma unroll
        for (int n16 = 0; n16 < 16; n16++) {
            uint32_t off = (uint32_t)((n16 * 16 + lrow) * 80) + lcol2;
            uint32_t kh0[4], kh1[4], kl0[4], kl1[4];
            uint32_t bh0[4], bh1[4], bl0[4], bl1[4];
            ldsm4(kh0, sb + AS_KHI + off); ldsm4(kh1, sb + AS_KHI + off + 32);
            ldsm4(kl0, sb + AS_KLO + off); ldsm4(kl1, sb + AS_KLO + off + 32);
            ldsm4(bh0, sb + AS_BKH + off); ldsm4(bh1, sb + AS_BKH + off + 32);
            ldsm4(bl0, sb + AS_BKL + off); ldsm4(bl1, sb + AS_BKL + off + 32);
            float4& cA = sc[2 * n16];
            float4& cB = sc[2 * n16 + 1];
            mma16816(cA, aqh[0], kh0[0], kh0[1]); mma16816(cA, aqh[1], kh1[0], kh1[1]);
            mma16816(cA, aql[0], kh0[0], kh0[1]); mma16816(cA, aql[1], kh1[0], kh1[1]);
            mma16816(cA, aqh[0], kl0[0], kl0[1]); mma16816(cA, aqh[1], kl1[0], kl1[1]);
            mma16816(cA, abh[0], bh0[0], bh0[1]); mma16816(cA, abh[1], bh1[0], bh1[1]);
            mma16816(cA, abl[0], bh0[0], bh0[1]); mma16816(cA, abl[1], bh1[0], bh1[1]);
            mma16816(cA, abh[0], bl0[0], bl0[1]); mma16816(cA, abh[1], bl1[0], bl1[1]);
            mma16816(cB, aqh[0], kh0[2], kh0[3]); mma16816(cB, aqh[1], kh1[2], kh1[3]);
            mma16816(cB, aql[0], kh0[2], kh0[3]); mma16816(cB, aql[1], kh1[2], kh1[3]);
            mma16816(cB, aqh[0], kl0[2], kl0[3]); mma16816(cB, aqh[1], kl1[2], kl1[3]);
            mma16816(cB, abh[0], bh0[2], bh0[3]); mma16816(cB, abh[1], bh1[2], bh1[3]);
            mma16816(cB, abl[0], bh0[2], bh0[3]); mma16816(cB, abl[1], bh1[2], bh1[3]);
            mma16816(cB, abh[0], bl0[2], bl0[3]); mma16816(cB, abh[1], bl1[2], bl1[3]);
        }

        float m0 = -1e30f, m1 = -1e30f;
        #pragma unroll
        for (int i = 0; i < 32; i++) {
            m0 = fmaxf(m0, fmaxf(sc[i].x, sc[i].y));
            m1 = fmaxf(m1, fmaxf(sc[i].z, sc[i].w));
        }
        m0 = fmaxf(m0, __shfl_xor_sync(0xffffffffu, m0, 1));
        m0 = fmaxf(m0, __shfl_xor_sync(0xffffffffu, m0, 2));
        m1 = fmaxf(m1, __shfl_xor_sync(0xffffffffu, m1, 1));
        m1 = fmaxf(m1, __shfl_xor_sync(0xffffffffu, m1, 2));
        float s0 = 0.f, s1 = 0.f;
        #pragma unroll
        for (int i = 0; i < 32; i++) {
            sc[i].x = __expf(sc[i].x - m0); sc[i].y = __expf(sc[i].y - m0);
            sc[i].z = __expf(sc[i].z - m1); sc[i].w = __expf(sc[i].w - m1);
            s0 += sc[i].x + sc[i].y; s1 += sc[i].z + sc[i].w;
        }
        s0 += __shfl_xor_sync(0xffffffffu, s0, 1);
        s0 += __shfl_xor_sync(0xffffffffu, s0, 2);
        s1 += __shfl_xor_sync(0xffffffffu, s1, 1);
        s1 += __shfl_xor_sync(0xffffffffu, s1, 2);
        float inv0 = 1.0f / s0, inv1 = 1.0f / s1;

        float4 o[4];
        #pragma unroll
        for (int i = 0; i < 4; i++) o[i] = make_float4(0.f, 0.f, 0.f, 0.f);
        #pragma unroll
        for (int tk = 0; tk < 16; tk++) {
            uint32_t Ahi[4], Alo[4];
            split2(sc[2 * tk].x,     sc[2 * tk].y,     Ahi[0], Alo[0]);
            split2(sc[2 * tk].z,     sc[2 * tk].w,     Ahi[1], Alo[1]);
            split2(sc[2 * tk + 1].x, sc[2 * tk + 1].y, Ahi[2], Alo[2]);
            split2(sc[2 * tk + 1].z, sc[2 * tk + 1].w, Ahi[3], Alo[3]);
            uint32_t off = (uint32_t)((tk * 16 + lrowT) * 80) + lcolT2;
            uint32_t vh0[4], vh1[4], vl0[4], vl1[4];
            ldsm4t(vh0, sb + AS_VHI + off); ldsm4t(vh1, sb + AS_VHI + off + 32);
            ldsm4t(vl0, sb + AS_VLO + off); ldsm4t(vl1, sb + AS_VLO + off + 32);
            mma16816(o[0], Ahi, vh0[0], vh0[1]); mma16816(o[1], Ahi, vh0[2], vh0[3]);
            mma16816(o[2], Ahi, vh1[0], vh1[1]); mma16816(o[3], Ahi, vh1[2], vh1[3]);
            mma16816(o[0], Alo, vh0[0], vh0[1]); mma16816(o[1], Alo, vh0[2], vh0[3]);
            mma16816(o[2], Alo, vh1[0], vh1[1]); mma16816(o[3], Alo, vh1[2], vh1[3]);
            mma16816(o[0], Ahi, vl0[0], vl0[1]); mma16816(o[1], Ahi, vl0[2], vl0[3]);
            mma16816(o[2], Ahi, vl1[0], vl1[1]); mma16816(o[3], Ahi, vl1[2], vl1[3]);
        }

        const float* vmean = (const float*)(sm + AS_VMEAN);
        float* out0 = g_att + ((size_t)b * 256 + tok0) * 256 + h * 32;
        float* out1 = out0 + 8 * 256;
        #pragma unroll
        for (int dt = 0; dt < 4; dt++) {
            int d = dt * 8 + cc;
            float vm0 = vmean[d], vm1 = vmean[d + 1];
            *(float2*)(out0 + d) = make_float2(o[dt].x * inv0 + vm0, o[dt].y * inv0 + vm1);
            *(float2*)(out1 + d) = make_float2(o[dt].z * inv1 + vm0, o[dt].w * inv1 + vm1);
        }
    }
}

// ---------------- launch -----------------------------------------------------
extern "C" void kernel_launch(void* const* d_in, const int* in_sizes, int n_in,
                              void* d_out, int out_size) {
    const float* x             = (const float*)d_in[0];
    const float* qkv_w         = (const float*)d_in[1];
    const float* qkv_b         = (const float*)d_in[2];
    const float* proj_w        = (const float*)d_in[3];
    const float* proj_b        = (const float*)d_in[4];
    const float* logit_scale   = (const float*)d_in[5];
    const float* val_res_scale = (const float*)d_in[6];
    const float* mlp1_w        = (const float*)d_in[7];
    const float* mlp1_b        = (const float*)d_in[8];
    const float* mlp2_w        = (const float*)d_in[9];
    const float* bias_scale    = (const float*)d_in[10];
    float* out = (float*)d_out;

    cudaFuncSetAttribute(attn_mma_kernel, cudaFuncAttributeMaxDynamicSharedMemorySize,
                         ATTN_SMEM_BYTES);
    cudaFuncSetAttribute(gemm_mma_kernel<true>, cudaFuncAttributeMaxDynamicSharedMemorySize,
                         GEMM_SMEM_BYTES);
    cudaFuncSetAttribute(gemm_mma_kernel<false>, cudaFuncAttributeMaxDynamicSharedMemorySize,
                         GEMM_SMEM_BYTES);

    prep_w_kernel<<<1024, 256>>>(qkv_w, proj_w);
    bias_mlp_kernel<<<256, 128>>>(mlp1_w, mlp1_b, mlp2_w, bias_scale);
    gemm_mma_kernel<true><<<dim3(6, 1024), 256, GEMM_SMEM_BYTES>>>(
        x, qkv_b, logit_scale, nullptr);
    attn_mma_kernel<<<4096, 256, ATTN_SMEM_BYTES>>>(val_res_scale);
    gemm_mma_kernel<false><<<dim3(2, 1024), 256, GEMM_SMEM_BYTES>>>(
        x /*unused*/, proj_b, nullptr, out);
}

// round 10
// speedup vs baseline: 2.9810x; 1.1522x over previous
#include <cuda_runtime.h>
#include <cuda_bf16.h>
#include <math.h>
#include <stdint.h>

#define BDIM 512
#define NTOK 256
#define HNUM 8
#define HD   32

// ---------------- scratch (device globals; referenced ONLY in device code) --
__device__ __align__(256) __nv_bfloat16 g_qh[BDIM*HNUM*NTOK*HD];
__device__ __align__(256) __nv_bfloat16 g_ql[BDIM*HNUM*NTOK*HD];
__device__ __align__(256) __nv_bfloat16 g_kh[BDIM*HNUM*NTOK*HD];
__device__ __align__(256) __nv_bfloat16 g_vh[BDIM*HNUM*NTOK*HD];
__device__ __align__(256) __nv_bfloat16 g_vl[BDIM*HNUM*NTOK*HD];
__device__ __align__(256) float g_att[BDIM*NTOK*256];                // 134 MB
__device__ __align__(256) __nv_bfloat16 g_wqkv_hi[768*256];
__device__ __align__(256) __nv_bfloat16 g_wqkv_lo[768*256];
__device__ __align__(256) __nv_bfloat16 g_wp_hi[256*256];
__device__ __align__(256) __nv_bfloat16 g_wp_lo[256*256];
__device__ __align__(256) __nv_bfloat16 g_bqh[HNUM*NTOK*HD];
__device__ __align__(256) __nv_bfloat16 g_bql[HNUM*NTOK*HD];
__device__ __align__(256) __nv_bfloat16 g_bkh[HNUM*NTOK*HD];
__device__ __align__(256) __nv_bfloat16 g_bkl[HNUM*NTOK*HD];

// ---------------- helpers ----------------------------------------------------
__device__ __forceinline__ uint32_t smem_u32(const void* p) {
    uint32_t a;
    asm("{ .reg .u64 t; cvta.to.shared.u64 t, %1; cvt.u32.u64 %0, t; }" : "=r"(a) : "l"(p));
    return a;
}
__device__ __forceinline__ uint32_t packbf(float x, float y) {
    uint32_t r;
    asm("cvt.rn.bf16x2.f32 %0, %1, %2;" : "=r"(r) : "f"(y), "f"(x));
    return r;
}
__device__ __forceinline__ void split2(float x, float y, uint32_t& hi, uint32_t& lo) {
    hi = packbf(x, y);
    float hx = __uint_as_float(hi << 16);
    float hy = __uint_as_float(hi & 0xffff0000u);
    lo = packbf(x - hx, y - hy);
}
__device__ __forceinline__ void ldsm4(uint32_t (&r)[4], uint32_t a) {
    asm volatile("ldmatrix.sync.aligned.m8n8.x4.shared.b16 {%0,%1,%2,%3}, [%4];"
        : "=r"(r[0]), "=r"(r[1]), "=r"(r[2]), "=r"(r[3]) : "r"(a));
}
__device__ __forceinline__ void ldsm4t(uint32_t (&r)[4], uint32_t a) {
    asm volatile("ldmatrix.sync.aligned.m8n8.x4.trans.shared.b16 {%0,%1,%2,%3}, [%4];"
        : "=r"(r[0]), "=r"(r[1]), "=r"(r[2]), "=r"(r[3]) : "r"(a));
}
__device__ __forceinline__ void mma16816(float4& c, const uint32_t (&a)[4],
                                         uint32_t b0, uint32_t b1) {
    asm volatile("mma.sync.aligned.m16n8k16.row.col.f32.bf16.bf16.f32 "
        "{%0,%1,%2,%3}, {%4,%5,%6,%7}, {%8,%9}, {%0,%1,%2,%3};"
        : "+f"(c.x), "+f"(c.y), "+f"(c.z), "+f"(c.w)
        : "r"(a[0]), "r"(a[1]), "r"(a[2]), "r"(a[3]), "r"(b0), "r"(b1));
}
__device__ __forceinline__ void cpasync16(uint32_t dst, const void* src) {
    asm volatile("cp.async.cg.shared.global [%0], [%1], 16;" :: "r"(dst), "l"(src));
}
#define CP_COMMIT() asm volatile("cp.async.commit_group;" ::: "memory")
#define CP_WAIT(n)  asm volatile("cp.async.wait_group %0;" :: "n"(n) : "memory")

// ---------------- kernel 0: weight transpose + bf16 split -------------------
__global__ __launch_bounds__(256) void prep_w_kernel(
    const float* __restrict__ qkv_w, const float* __restrict__ proj_w) {
    int idx = blockIdx.x * 256 + threadIdx.x;
    if (idx < 196608) {
        int n = idx >> 8, k = idx & 255;
        float v = qkv_w[k * 768 + n];
        __nv_bfloat16 h = __float2bfloat16(v);
        g_wqkv_hi[idx] = h;
        g_wqkv_lo[idx] = __float2bfloat16(v - __bfloat162float(h));
    } else {
        int j = idx - 196608;
        int n = j >> 8, k = j & 255;
        float v = proj_w[k * 256 + n];
        __nv_bfloat16 h = __float2bfloat16(v);
        g_wp_hi[j] = h;
        g_wp_lo[j] = __float2bfloat16(v - __bfloat162float(h));
    }
}

// ---------------- kernel 1: MLP -> bq, bk (bf16 hi/lo) ----------------------
__global__ __launch_bounds__(128) void bias_mlp_kernel(
    const float* __restrict__ m1w, const float* __restrict__ m1b,
    const float* __restrict__ m2w, const float* __restrict__ bs) {
    __shared__ float hf[128];
    const int n = blockIdx.x;
    const int t = threadIdx.x;
    const float invden = 1.0f / log1pf(15.0f);
    const float cy = log1pf((float)(n >> 4)) * invden;
    const float cx = log1pf((float)(n & 15)) * invden;
    {
        float z = cy * m1w[t] + cx * m1w[128 + t] + m1b[t];
        hf[t] = 0.5f * z * (1.0f + erff(z * 0.70710678118654752f));
    }
    __syncthreads();
    const float bscale = bs[0];
    for (int c = t; c < 512; c += 128) {
        float acc = 0.0f;
        #pragma unroll 8
        for (int j = 0; j < 128; j++) acc += hf[j] * m2w[j * 512 + c];
        float sig = 1.0f / (1.0f + __expf(-acc));
        int h = c >> 6, s = (c >> 5) & 1, r = c & 31;
        float v = (s == 0) ? bscale * sig : sig;
        __nv_bfloat16 vh = __float2bfloat16(v);
        __nv_bfloat16 vl = __float2bfloat16(v - __bfloat162float(vh));
        int idx = (h * NTOK + n) * 32 + r;
        if (s == 0) { g_bqh[idx] = vh; g_bql[idx] = vl; }
        else        { g_bkh[idx] = vh; g_bkl[idx] = vl; }
    }
}

// ---------------- GEMM via mma.sync, n128 tile, selective B-lo, cp.async ----
// smem per buffer: hi[128][40bf16]=10240 + lo=10240 -> 20480; x2 = 40960
#define GEMM_BUF_BYTES 20480
#define GEMM_SMEM_BYTES (2 * GEMM_BUF_BYTES)

template <bool QKV>
__global__ __launch_bounds__(256, 2) void gemm_mma_kernel(
    const float* __restrict__ Ain, const float* __restrict__ bias,
    const float* __restrict__ ls, float* __restrict__ outp) {
    extern __shared__ char sm[];
    const uint32_t sb = smem_u32(sm);
    const int t = threadIdx.x, w = t >> 5, lane = t & 31;
    const int m0 = blockIdx.y * 128 + w * 16;
    const int c0 = blockIdx.x * 128;
    const int r = lane >> 2, cc = (lane & 3) * 2;
    const int lrow = (lane & 7) + ((lane >> 4) << 3);
    const int lcol2 = (((lane >> 3) & 1) << 3) * 2;

    const float* A = QKV ? Ain : (const float*)g_att;
    const __nv_bfloat16* Bh = QKV ? g_wqkv_hi : g_wp_hi;
    const __nv_bfloat16* Bl = QKV ? g_wqkv_lo : g_wp_lo;
    // value path needs B-lo (v blocks of QKV; all of proj). logit path skips it.
    const bool need_lo = QKV ? (blockIdx.x >= 4) : true;

    float4 acc[16];
    #pragma unroll
    for (int i = 0; i < 16; i++) acc[i] = make_float4(0.f, 0.f, 0.f, 0.f);

    const float* ar0 = A + (size_t)(m0 + r) * 256;
    const float* ar8 = ar0 + 8 * 256;

    // staging: 2 threads per row; thread covers 32B (2x16B) of the 64B chunk
    const int srow = t >> 1;
    const int half = t & 1;
    const __nv_bfloat16* bhsrc = Bh + (size_t)(c0 + srow) * 256 + half * 16;
    const __nv_bfloat16* blsrc = Bl + (size_t)(c0 + srow) * 256 + half * 16;
    const uint32_t sdst = sb + srow * 80 + half * 32;

    // prologue: stage chunk 0 -> buf0
    cpasync16(sdst, bhsrc);
    cpasync16(sdst + 16, bhsrc + 8);
    if (need_lo) {
        cpasync16(sdst + 10240, blsrc);
        cpasync16(sdst + 10240 + 16, blsrc + 8);
    }
    CP_COMMIT();

    #pragma unroll
    for (int kc = 0; kc < 8; kc++) {
        if (kc < 7) {
            uint32_t dst = sdst + ((kc + 1) & 1) * GEMM_BUF_BYTES;
            const __nv_bfloat16* srch = bhsrc + (kc + 1) * 32;
            cpasync16(dst, srch);
            cpasync16(dst + 16, srch + 8);
            if (need_lo) {
                const __nv_bfloat16* srcl = blsrc + (kc + 1) * 32;
                cpasync16(dst + 10240, srcl);
                cpasync16(dst + 10240 + 16, srcl + 8);
            }
            CP_COMMIT();
        }
        // A chunk kc: load + split (overlaps with cp.async)
        uint32_t ah[2][4], al[2][4];
        {
            int k0 = kc * 32 + cc;
            float2 v;
            #pragma unroll
            for (int kk = 0; kk < 2; kk++) {
                int o = k0 + kk * 16;
                v = *(const float2*)(ar0 + o);      split2(v.x, v.y, ah[kk][0], al[kk][0]);
                v = *(const float2*)(ar8 + o);      split2(v.x, v.y, ah[kk][1], al[kk][1]);
                v = *(const float2*)(ar0 + o + 8);  split2(v.x, v.y, ah[kk][2], al[kk][2]);
                v = *(const float2*)(ar8 + o + 8);  split2(v.x, v.y, ah[kk][3], al[kk][3]);
            }
        }
        if (kc < 7) CP_WAIT(1); else CP_WAIT(0);
        __syncthreads();

        const uint32_t bufb = sb + (kc & 1) * GEMM_BUF_BYTES;
        #pragma unroll
        for (int n16 = 0; n16 < 8; n16++) {
            uint32_t off = (uint32_t)((n16 * 16 + lrow) * 80) + lcol2;
            uint32_t rh0[4], rh1[4];
            ldsm4(rh0, bufb + off);
            ldsm4(rh1, bufb + off + 32);
            float4& cA = acc[2 * n16];
            float4& cB = acc[2 * n16 + 1];
            mma16816(cA, ah[0], rh0[0], rh0[1]); mma16816(cA, ah[1], rh1[0], rh1[1]);
            mma16816(cA, al[0], rh0[0], rh0[1]); mma16816(cA, al[1], rh1[0], rh1[1]);
            mma16816(cB, ah[0], rh0[2], rh0[3]); mma16816(cB, ah[1], rh1[2], rh1[3]);
            mma16816(cB, al[0], rh0[2], rh0[3]); mma16816(cB, al[1], rh1[2], rh1[3]);
            if (need_lo) {
                uint32_t rl0[4], rl1[4];
                ldsm4(rl0, bufb + 10240 + off);
                ldsm4(rl1, bufb + 10240 + off + 32);
                mma16816(cA, ah[0], rl0[0], rl0[1]); mma16816(cA, ah[1], rl1[0], rl1[1]);
                mma16816(cB, ah[0], rl0[2], rl0[3]); mma16816(cB, ah[1], rl1[2], rl1[3]);
            }
        }
        __syncthreads();
    }

    const int mrow0 = m0 + r;
    if (QKV) {
        const int s = blockIdx.x >> 1;
        __nv_bfloat16* dh = (s == 0) ? g_qh : (s == 1 ? g_kh : g_vh);
        const int bidx = mrow0 >> 8, n0r = mrow0 & 255, n1r = n0r + 8;
        #pragma unroll
        for (int ti = 0; ti < 16; ti++) {
            int c = c0 + ti * 8 + cc;
            float2 bb = *(const float2*)(bias + c);
            int rem = c & 255;
            int h = rem >> 5, d = rem & 31;
            float scv = (s == 0) ? __ldg(ls + h) : 1.0f;
            float v00 = (acc[ti].x + bb.x) * scv, v01 = (acc[ti].y + bb.y) * scv;
            float v10 = (acc[ti].z + bb.x) * scv, v11 = (acc[ti].w + bb.y) * scv;
            size_t i0 = ((size_t)(bidx * 8 + h) * 256 + n0r) * 32 + d;
            size_t i1 = ((size_t)(bidx * 8 + h) * 256 + n1r) * 32 + d;
            uint32_t hi, lo;
            split2(v00, v01, hi, lo);
            *(uint32_t*)&dh[i0] = hi;
            if (s == 0) *(uint32_t*)&g_ql[i0] = lo;
            else if (s == 2) *(uint32_t*)&g_vl[i0] = lo;
            split2(v10, v11, hi, lo);
            *(uint32_t*)&dh[i1] = hi;
            if (s == 0) *(uint32_t*)&g_ql[i1] = lo;
            else if (s == 2) *(uint32_t*)&g_vl[i1] = lo;
        }
    } else {
        #pragma unroll
        for (int ti = 0; ti < 16; ti++) {
            int c = c0 + ti * 8 + cc;
            float2 bb = *(const float2*)(bias + c);
            *(float2*)(outp + (size_t)mrow0 * 256 + c) =
                make_float2(acc[ti].x + bb.x, acc[ti].y + bb.y);
            *(float2*)(outp + (size_t)(mrow0 + 8) * 256 + c) =
                make_float2(acc[ti].z + bb.x, acc[ti].w + bb.y);
        }
    }
}

// ---------------- attention kernel: K hi-only, V hi+lo, bk 3-term -----------
#define AS_KHI   0
#define AS_BKH   20480
#define AS_BKL   40960
#define AS_VHI   61440
#define AS_VLO   81920
#define AS_VMEAN 102400
#define AS_RED   102528
#define ATTN_SMEM_BYTES (102528 + 1024 + 512)

__global__ __launch_bounds__(256) void attn_mma_kernel(const float* __restrict__ vrs) {
    extern __shared__ char sm[];
    const uint32_t sb = smem_u32(sm);
    const int bh = blockIdx.x;
    const int b = bh >> 3, h = bh & 7;
    const int t = threadIdx.x, w = t >> 5, lane = t & 31;
    const int r = lane >> 2, cc = (lane & 3) * 2;
    const int lrow = (lane & 7) + ((lane >> 4) << 3);
    const int lcol2 = (((lane >> 3) & 1) << 3) * 2;
    const int lrowT = lane & 15;
    const int lcolT2 = ((lane >> 4) << 3) * 2;

    {
        size_t gk = (size_t)bh * 8192 + (size_t)t * 32;
        size_t gb = (size_t)h * 8192 + (size_t)t * 32;
        #pragma unroll
        for (int u = 0; u < 4; u++) {
            *(uint4*)(sm + AS_KHI + t * 80 + u * 16) = *(const uint4*)(g_kh + gk + u * 8);
            *(uint4*)(sm + AS_VHI + t * 80 + u * 16) = *(const uint4*)(g_vh + gk + u * 8);
            *(uint4*)(sm + AS_VLO + t * 80 + u * 16) = *(const uint4*)(g_vl + gk + u * 8);
            *(uint4*)(sm + AS_BKH + t * 80 + u * 16) = *(const uint4*)(g_bkh + gb + u * 8);
            *(uint4*)(sm + AS_BKL + t * 80 + u * 16) = *(const uint4*)(g_bkl + gb + u * 8);
        }
    }
    __syncthreads();

    {
        int d = t & 31, grp = t >> 5;
        float s = 0.0f;
        for (int n = grp * 32; n < grp * 32 + 32; n++) {
            uint16_t hv = *(const uint16_t*)(sm + AS_VHI + n * 80 + d * 2);
            uint16_t lv = *(const uint16_t*)(sm + AS_VLO + n * 80 + d * 2);
            s += __uint_as_float(((uint32_t)hv) << 16) + __uint_as_float(((uint32_t)lv) << 16);
        }
        ((float*)(sm + AS_RED))[grp * 32 + d] = s;
    }
    __syncthreads();
    if (t < 32) {
        float s = 0.0f;
        #pragma unroll
        for (int g = 0; g < 8; g++) s += ((float*)(sm + AS_RED))[g * 32 + t];
        ((float*)(sm + AS_VMEAN))[t] = s * (1.0f / 256.0f) * __ldg(vrs + h);
    }
    __syncthreads();

    for (int pass = 0; pass < 2; pass++) {
        const int tok0 = pass * 128 + w * 16 + r;
        uint32_t aqh[2][4], aql[2][4], abh[2][4], abl[2][4];
        {
            size_t q0 = (size_t)bh * 8192 + (size_t)tok0 * 32;
            size_t b0 = (size_t)h * 8192 + (size_t)tok0 * 32;
            #pragma unroll
            for (int kk = 0; kk < 2; kk++) {
                int o = kk * 16 + cc;
                aqh[kk][0] = *(const uint32_t*)(g_qh + q0 + o);
                aqh[kk][1] = *(const uint32_t*)(g_qh + q0 + 256 + o);
                aqh[kk][2] = *(const uint32_t*)(g_qh + q0 + o + 8);
                aqh[kk][3] = *(const uint32_t*)(g_qh + q0 + 256 + o + 8);
                aql[kk][0] = *(const uint32_t*)(g_ql + q0 + o);
                aql[kk][1] = *(const uint32_t*)(g_ql + q0 + 256 + o);
                aql[kk][2] = *(const uint32_t*)(g_ql + q0 + o + 8);
                aql[kk][3] = *(const uint32_t*)(g_ql + q0 + 256 + o + 8);
                abh[kk][0] = *(const uint32_t*)(g_bqh + b0 + o);
                abh[kk][1] = *(const uint32_t*)(g_bqh + b0 + 256 + o);
                abh[kk][2] = *(const uint32_t*)(g_bqh + b0 + o + 8);
                abh[kk][3] = *(const uint32_t*)(g_bqh + b0 + 256 + o + 8);
                abl[kk][0] = *(const uint32_t*)(g_bql + b0 + o);
                abl[kk][1] = *(const uint32_t*)(g_bql + b0 + 256 + o);
                abl[kk][2] = *(const uint32_t*)(g_bql + b0 + o + 8);
                abl[kk][3] = *(const uint32_t*)(g_bql + b0 + 256 + o + 8);
            }
        }

        float4 sc[32];
        #pragma unroll
        for (int i = 0; i < 32; i++) sc[i] = make_float4(0.f, 0.f, 0.f, 0.f);
        #pragma unroll
        for (int n16 = 0; n16 < 16; n16++) {
            uint32_t off = (uint32_t)((n16 * 16 + lrow) * 80) + lcol2;
            uint32_t kh0[4], kh1[4];
            uint32_t bh0[4], bh1[4], bl0[4], bl1[4];
            ldsm4(kh0, sb + AS_KHI + off); ldsm4(kh1, sb + AS_KHI + off + 32);
            ldsm4(bh0, sb + AS_BKH + off); ldsm4(bh1, sb + AS_BKH + off + 32);
            ldsm4(bl0, sb + AS_BKL + off); ldsm4(bl1, sb + AS_BKL + off + 32);
            float4& cA = sc[2 * n16];
            float4& cB = sc[2 * n16 + 1];
            mma16816(cA, aqh[0], kh0[0], kh0[1]); mma16816(cA, aqh[1], kh1[0], kh1[1]);
            mma16816(cA, aql[0], kh0[0], kh0[1]); mma16816(cA, aql[1], kh1[0], kh1[1]);
            mma16816(cA, abh[0], bh0[0], bh0[1]); mma16816(cA, abh[1], bh1[0], bh1[1]);
            mma16816(cA, abl[0], bh0[0], bh0[1]); mma16816(cA, abl[1], bh1[0], bh1[1]);
            mma16816(cA, abh[0], bl0[0], bl0[1]); mma16816(cA, abh[1], bl1[0], bl1[1]);
            mma16816(cB, aqh[0], kh0[2], kh0[3]); mma16816(cB, aqh[1], kh1[2], kh1[3]);
            mma16816(cB, aql[0], kh0[2], kh0[3]); mma16816(cB, aql[1], kh1[2], kh1[3]);
            mma16816(cB, abh[0], bh0[2], bh0[3]); mma16816(cB, abh[1], bh1[2], bh1[3]);
            mma16816(cB, abl[0], bh0[2], bh0[3]); mma16816(cB, abl[1], bh1[2], bh1[3]);
            mma16816(cB, abh[0], bl0[2], bl0[3]); mma16816(cB, abh[1], bl1[2], bl1[3]);
        }

        float m0 = -1e30f, m1 = -1e30f;
        #pragma unroll
        for (int i = 0; i < 32; i++) {
            m0 = fmaxf(m0, fmaxf(sc[i].x, sc[i].y));
            m1 = fmaxf(m1, fmaxf(sc[i].z, sc[i].w));
        }
        m0 = fmaxf(m0, __shfl_xor_sync(0xffffffffu, m0, 1));
        m0 = fmaxf(m0, __shfl_xor_sync(0xffffffffu, m0, 2));
        m1 = fmaxf(m1, __shfl_xor_sync(0xffffffffu, m1, 1));
        m1 = fmaxf(m1, __shfl_xor_sync(0xffffffffu, m1, 2));
        float s0 = 0.f, s1 = 0.f;
        #pragma unroll
        for (int i = 0; i < 32; i++) {
            sc[i].x = __expf(sc[i].x - m0); sc[i].y = __expf(sc[i].y - m0);
            sc[i].z = __expf(sc[i].z - m1); sc[i].w = __expf(sc[i].w - m1);
            s0 += sc[i].x + sc[i].y; s1 += sc[i].z + sc[i].w;
        }
        s0 += __shfl_xor_sync(0xffffffffu, s0, 1);
        s0 += __shfl_xor_sync(0xffffffffu, s0, 2);
        s1 += __shfl_xor_sync(0xffffffffu, s1, 1);
        s1 += __shfl_xor_sync(0xffffffffu, s1, 2);
        float inv0 = 1.0f / s0, inv1 = 1.0f / s1;

        float4 o[4];
        #pragma unroll
        for (int i = 0; i < 4; i++) o[i] = make_float4(0.f, 0.f, 0.f, 0.f);
        #pragma unroll
        for (int tk = 0; tk < 16; tk++) {
            uint32_t Ahi[4], Alo[4];
            split2(sc[2 * tk].x,     sc[2 * tk].y,     Ahi[0], Alo[0]);
            split2(sc[2 * tk].z,     sc[2 * tk].w,     Ahi[1], Alo[1]);
            split2(sc[2 * tk + 1].x, sc[2 * tk + 1].y, Ahi[2], Alo[2]);
            split2(sc[2 * tk + 1].z, sc[2 * tk + 1].w, Ahi[3], Alo[3]);
            uint32_t off = (uint32_t)((tk * 16 + lrowT) * 80) + lcolT2;
            uint32_t vh0[4], vh1[4], vl0[4], vl1[4];
            ldsm4t(vh0, sb + AS_VHI + off); ldsm4t(vh1, sb + AS_VHI + off + 32);
            ldsm4t(vl0, sb + AS_VLO + off); ldsm4t(vl1, sb + AS_VLO + off + 32);
            mma16816(o[0], Ahi, vh0[0], vh0[1]); mma16816(o[1], Ahi, vh0[2], vh0[3]);
            mma16816(o[2], Ahi, vh1[0], vh1[1]); mma16816(o[3], Ahi, vh1[2], vh1[3]);
            mma16816(o[0], Alo, vh0[0], vh0[1]); mma16816(o[1], Alo, vh0[2], vh0[3]);
            mma16816(o[2], Alo, vh1[0], vh1[1]); mma16816(o[3], Alo, vh1[2], vh1[3]);
            mma16816(o[0], Ahi, vl0[0], vl0[1]); mma16816(o[1], Ahi, vl0[2], vl0[3]);
            mma16816(o[2], Ahi, vl1[0], vl1[1]); mma16816(o[3], Ahi, vl1[2], vl1[3]);
        }

        const float* vmean = (const float*)(sm + AS_VMEAN);
        float* out0 = g_att + ((size_t)b * 256 + tok0) * 256 + h * 32;
        float* out1 = out0 + 8 * 256;
        #pragma unroll
        for (int dt = 0; dt < 4; dt++) {
            int d = dt * 8 + cc;
            float vm0 = vmean[d], vm1 = vmean[d + 1];
            *(float2*)(out0 + d) = make_float2(o[dt].x * inv0 + vm0, o[dt].y * inv0 + vm1);
            *(float2*)(out1 + d) = make_float2(o[dt].z * inv1 + vm0, o[dt].w * inv1 + vm1);
        }
    }
}

// ---------------- launch -----------------------------------------------------
extern "C" void kernel_launch(void* const* d_in, const int* in_sizes, int n_in,
                              void* d_out, int out_size) {
    const float* x             = (const float*)d_in[0];
    const float* qkv_w         = (const float*)d_in[1];
    const float* qkv_b         = (const float*)d_in[2];
    const float* proj_w        = (const float*)d_in[3];
    const float* proj_b        = (const float*)d_in[4];
    const float* logit_scale   = (const float*)d_in[5];
    const float* val_res_scale = (const float*)d_in[6];
    const float* mlp1_w        = (const float*)d_in[7];
    const float* mlp1_b        = (const float*)d_in[8];
    const float* mlp2_w        = (const float*)d_in[9];
    const float* bias_scale    = (const float*)d_in[10];
    float* out = (float*)d_out;

    cudaFuncSetAttribute(attn_mma_kernel, cudaFuncAttributeMaxDynamicSharedMemorySize,
                         ATTN_SMEM_BYTES);
    cudaFuncSetAttribute(gemm_mma_kernel<true>, cudaFuncAttributeMaxDynamicSharedMemorySize,
                         GEMM_SMEM_BYTES);
    cudaFuncSetAttribute(gemm_mma_kernel<false>, cudaFuncAttributeMaxDynamicSharedMemorySize,
                         GEMM_SMEM_BYTES);

    prep_w_kernel<<<1024, 256>>>(qkv_w, proj_w);
    bias_mlp_kernel<<<256, 128>>>(mlp1_w, mlp1_b, mlp2_w, bias_scale);
    gemm_mma_kernel<true><<<dim3(6, 1024), 256, GEMM_SMEM_BYTES>>>(
        x, qkv_b, logit_scale, nullptr);
    attn_mma_kernel<<<4096, 256, ATTN_SMEM_BYTES>>>(val_res_scale);
    gemm_mma_kernel<false><<<dim3(2, 1024), 256, GEMM_SMEM_BYTES>>>(
        x /*unused*/, proj_b, nullptr, out);
}